// round 12
// baseline (speedup 1.0000x reference)
#include <cuda_runtime.h>
#include <cuda_fp16.h>
#include <math.h>
#include <stdint.h>

// Problem constants (fixed shapes)
#define BB 4
#define TT 512
#define CC 512
#define WN 32
#define DD 512
#define PP 64

#define NT0_W0 (TT-8+1)          // 505
#define NT0_W1 (TT-16+1)         // 497
#define ROWS0 (BB*NT0_W0)        // 2020
#define ROWS1 (BB*NT0_W1)        // 1988
#define AOFF1 2048               // window-1 A/Md row offset (rows 2020..2047 stay zero)

// ---------------- scratch (static device globals; no allocation) ----------------
__device__ __half g_Xvh[BB*TT*CC], g_Xvl[BB*TT*CC];
__device__ __half g_Hh [BB*TT*CC], g_Hl [BB*TT*CC];
__device__ float g_V  [BB*TT*CC];
__device__ __half g_Xqh[BB*WN*CC], g_Xql[BB*WN*CC];
__device__ __half g_Hqh[BB*WN*2*CC], g_Hql[BB*WN*2*CC];   // [128, 1024]
__device__ float g_ep [BB*WN*2*CC];                        // [128, 1024] = [E1 | E2]
__device__ float g_sim[BB*TT*WN];
__device__ float g_cum[BB*(TT+1)*CC];
__device__ float g_parts[BB*8*CC];
__device__ __half g_Ah[4096*CC], g_Al[4096*CC];   // zero-init; pad rows never written
__device__ float g_Md [4096*DD];
__device__ float g_pool[2*BB*PP*DD];               // per-window buffers
__device__ float g_part[4*64*BB*PP];
__device__ __half g_w1h[CC*CC],   g_w1l[CC*CC];    // vid_w1^T
__device__ __half g_w2h[CC*CC],   g_w2l[CC*CC];    // vid_w2^T
__device__ __half g_pwh[CC*DD],   g_pwl[CC*DD];    // proj_w^T
__device__ __half g_wq1h[2*CC*CC],g_wq1l[2*CC*CC]; // [s1_w1^T ; s2_w1^T]
__device__ __half g_wq2h[2*CC*CC],g_wq2l[2*CC*CC]; // [s1_w2^T ; s2_w2^T]
__device__ float g_bq1[2*CC];                       // [s1_b1 ; s2_b1]
__device__ float g_bq2[2*CC];                       // [s1_b2 ; s2_b2]

static inline int cdiv(int a, int b){ return (a + b - 1) / b; }

// ---------------- mma.sync helpers (sm_80+ path; legal on plain sm_100) ----------------
__device__ __forceinline__ uint32_t smem_to_u32(const void* p) {
    uint32_t a;
    asm("{ .reg .u64 tmp; cvta.to.shared.u64 tmp, %1; cvt.u32.u64 %0, tmp; }" : "=r"(a) : "l"(p));
    return a;
}
__device__ __forceinline__ void ldmx4(uint32_t* r, uint32_t addr){
    asm volatile("ldmatrix.sync.aligned.m8n8.x4.shared.b16 {%0,%1,%2,%3}, [%4];"
        : "=r"(r[0]),"=r"(r[1]),"=r"(r[2]),"=r"(r[3]) : "r"(addr));
}
__device__ __forceinline__ void mma16816(float* c, const uint32_t* a, uint32_t b0, uint32_t b1){
    asm volatile("mma.sync.aligned.m16n8k16.row.col.f32.f16.f16.f32 "
        "{%0,%1,%2,%3}, {%4,%5,%6,%7}, {%8,%9}, {%0,%1,%2,%3};"
        : "+f"(c[0]),"+f"(c[1]),"+f"(c[2]),"+f"(c[3])
        : "r"(a[0]),"r"(a[1]),"r"(a[2]),"r"(a[3]), "r"(b0),"r"(b1));
}
__device__ __forceinline__ void cp_async16(uint32_t saddr, const void* gaddr){
    asm volatile("cp.async.cg.shared.global [%0], [%1], 16;" :: "r"(saddr), "l"(gaddr));
}
// fp16 hi/lo split: hi+lo captures ~22 mantissa bits of v
__device__ __forceinline__ void split_h(float v, __half& h, __half& l){
    h = __float2half_rn(v);
    l = __float2half_rn(v - __half2float(h));
}

// ---------- tensor-core fp16-split GEMM: C = (Ah+Al)@(Bh+Bl)^T, 3 products ----------
// Block tile 64x64, 4 warps (2m x 2n), warp tile 32x32, K-chunk 32.
// 3-stage smem pipeline + fragment double-buffer. 4 CTAs/SM (128 threads).
// If n0 >= nswitch, A pointers shift by aoff elements (fuses two GEMMs along N).
#define GM_STG 16384
#define GM_SMEM (3*16384)

template<int RELU, int WF, int WS>
__global__ void __launch_bounds__(128, 4)
gemm_mma(const __half* __restrict__ Ah, const __half* __restrict__ Al,
         const __half* __restrict__ Bh, const __half* __restrict__ Bl,
         const float* __restrict__ bias, float* __restrict__ outF,
         __half* __restrict__ outH, __half* __restrict__ outL,
         int M, int N, int K, int lda, int ldb, int nswitch, int aoff)
{
    extern __shared__ char smem[];
    uint32_t sbase = smem_to_u32(smem);
    int tid = threadIdx.x;
    int warp = tid >> 5, lane = tid & 31;
    int wm = warp & 1, wn = warp >> 1;          // 2m x 2n warps
    int m0 = blockIdx.y << 6, n0 = blockIdx.x << 6;
    if (n0 >= nswitch){ Ah += aoff; Al += aoff; }

    float acc[2][4][4];
#pragma unroll
    for (int a = 0; a < 2; a++)
#pragma unroll
        for (int b = 0; b < 4; b++)
#pragma unroll
            for (int c = 0; c < 4; c++) acc[a][b][c] = 0.f;

    int nch = K >> 5;

    auto load_chunk = [&](int ch){
        int stage = ch % 3;
        int k0 = ch << 5;
#pragma unroll
        for (int j = 0; j < 8; j++){
            int i = tid + (j << 7);             // 0..1023
            int tile = i >> 8;                  // 0:Ah 1:Al 2:Bh 3:Bl
            int rem = i & 255;
            int g = rem >> 6, r = rem & 63;
            const __half* gp;
            if (tile < 2) gp = (tile ? Al : Ah) + (long)(m0 + r)*lda + k0 + (g << 3);
            else          gp = ((tile & 1) ? Bl : Bh) + (long)(n0 + r)*ldb + k0 + (g << 3);
            uint32_t sa = sbase + stage*GM_STG + (tile << 12) + (g << 10) + (r << 4);
            cp_async16(sa, gp);
        }
        asm volatile("cp.async.commit_group;");
    };

    load_chunk(0);
    if (nch > 1) load_chunk(1);

    int ra = lane & 15;
    int ghalf = lane >> 4;

    for (int ch = 0; ch < nch; ch++){
        if (ch + 1 < nch) asm volatile("cp.async.wait_group 1;");
        else              asm volatile("cp.async.wait_group 0;");
        __syncthreads();
        if (ch + 2 < nch) load_chunk(ch + 2);

        uint32_t st = sbase + (ch % 3)*GM_STG;

        uint32_t a_h[2][2][4], a_l[2][2][4], b_h[2][2][4], b_l[2][2][4];

        auto load_frag = [&](int ks, int buf){
            int ga = (ks << 1) + ghalf;
#pragma unroll
            for (int mt = 0; mt < 2; mt++){
                int r = (wm << 5) + (mt << 4) + ra;
                uint32_t off = (uint32_t)((ga << 10) + (r << 4));
                ldmx4(a_h[buf][mt], st + off);
                ldmx4(a_l[buf][mt], st + 4096 + off);
            }
#pragma unroll
            for (int np = 0; np < 2; np++){
                int r = (wn << 5) + (np << 4) + ra;
                uint32_t off = (uint32_t)((ga << 10) + (r << 4));
                ldmx4(b_h[buf][np], st + 8192  + off);
                ldmx4(b_l[buf][np], st + 12288 + off);
            }
        };

        load_frag(0, 0);
#pragma unroll
        for (int ks = 0; ks < 2; ks++){
            int buf = ks & 1;
            if (ks == 0) load_frag(1, 1);
#pragma unroll
            for (int mt = 0; mt < 2; mt++)
#pragma unroll
                for (int nt = 0; nt < 4; nt++){
                    int np = nt >> 1, pr = nt & 1;
                    mma16816(acc[mt][nt], a_h[buf][mt], b_h[buf][np][pr], b_h[buf][np][pr+2]);
                    mma16816(acc[mt][nt], a_h[buf][mt], b_l[buf][np][pr], b_l[buf][np][pr+2]);
                    mma16816(acc[mt][nt], a_l[buf][mt], b_h[buf][np][pr], b_h[buf][np][pr+2]);
                }
        }
    }
    __syncthreads();

    // epilogue
    int col_base = n0 + (wn << 5);
    int r0 = lane >> 2;
    int cp2 = (lane & 3) << 1;
#pragma unroll
    for (int mt = 0; mt < 2; mt++){
        int row_base = m0 + (wm << 5) + (mt << 4);
#pragma unroll
        for (int i = 0; i < 2; i++){
            int m = row_base + r0 + (i << 3);
#pragma unroll
            for (int nt = 0; nt < 4; nt++){
                int col = col_base + (nt << 3) + cp2;
                float v0 = acc[mt][nt][i*2+0] + bias[col];
                float v1 = acc[mt][nt][i*2+1] + bias[col+1];
                if (RELU){ v0 = fmaxf(v0, 0.f); v1 = fmaxf(v1, 0.f); }
                if (WF){
                    float2 o; o.x = v0; o.y = v1;
                    *(float2*)&outF[(long)m*N + col] = o;
                }
                if (WS){
                    __half h0, l0, h1, l1;
                    split_h(v0, h0, l0);
                    split_h(v1, h1, l1);
                    *(__half2*)&outH[(long)m*N + col] = __halves2half2(h0, h1);
                    *(__half2*)&outL[(long)m*N + col] = __halves2half2(l0, l1);
                }
            }
        }
    }
}

// ---------------- small kernels ----------------

// PE add + fp16 split for vis (rows < 2048) and query (rows >= 2048)
__global__ void add_pe_split_all(const float* __restrict__ xv,
                                 __half* __restrict__ xvh, __half* __restrict__ xvl,
                                 const float* __restrict__ xq,
                                 __half* __restrict__ xqh, __half* __restrict__ xql){
    int row = blockIdx.x;
    int c = threadIdx.x;
    const float* x; __half *yh, *yl; int t;
    if (row < BB*TT){ x = xv; yh = xvh; yl = xvl; t = row % TT; }
    else { row -= BB*TT; x = xq; yh = xqh; yl = xql; t = row % WN; }
    int i2 = (c >> 1) << 1;
    float ang = (float)t * expf((float)i2 * -1.7988946039352293e-2f);
    float pe = (c & 1) ? cosf(ang) : sinf(ang);
    float v = x[row*CC + c] + pe;
    __half h, l; split_h(v, h, l);
    yh[row*CC + c] = h; yl[row*CC + c] = l;
}

// batched 512x512 transpose+split: z selects matrix
struct TSArgs { const float* src[7]; __half* dh[7]; __half* dl[7]; };
__global__ void transpose_split_all(TSArgs a){
    int z = blockIdx.z;
    const float* W = a.src[z];
    __half* Th = a.dh[z];
    __half* Tl = a.dl[z];
    __shared__ float t[32][33];
    int bx = blockIdx.x << 5, by = blockIdx.y << 5;
    int x = threadIdx.x, y = threadIdx.y;
#pragma unroll
    for (int i = 0; i < 32; i += 8) t[y+i][x] = W[(long)(by + y + i)*512 + bx + x];
    __syncthreads();
#pragma unroll
    for (int i = 0; i < 32; i += 8){
        float v = t[x][y+i];
        __half h, l; split_h(v, h, l);
        long o = (long)(bx + y + i)*512 + by + x;
        Th[o] = h; Tl[o] = l;
    }
}

// pack both fused biases in one launch (4 blocks x 512)
__global__ void pack_biases(const float* __restrict__ a1, const float* __restrict__ a2,
                            const float* __restrict__ b1, const float* __restrict__ b2,
                            float* __restrict__ dq1, float* __restrict__ dq2){
    int blk = blockIdx.x;
    int i = threadIdx.x;
    if (blk == 0) dq1[i] = a1[i];
    else if (blk == 1) dq1[512 + i] = a2[i];
    else if (blk == 2) dq2[i] = b1[i];
    else dq2[512 + i] = b2[i];
}

// sim[b, t, w] = dot(v[b,t,:], E1[b,w,:]); E1 = EP[:, 0:512] with row stride 1024
__global__ void sim_kernel(const float* __restrict__ V, const float* __restrict__ EP,
                           float* __restrict__ SIM){
    int t = blockIdx.x, b = blockIdx.y;
    __shared__ float vrow[CC];
    int tid = threadIdx.x;
    const float* vp = &V[(b*TT + t)*CC];
    vrow[tid]       = vp[tid];
    vrow[tid + 256] = vp[tid + 256];
    __syncthreads();
    int wid = tid >> 5, lane = tid & 31;
    for (int w = wid; w < WN; w += 8){
        const float* e = &EP[(b*WN + w)*(2*CC)];
        float sum = 0.f;
        for (int c = lane; c < CC; c += 32) sum = fmaf(vrow[c], e[c], sum);
#pragma unroll
        for (int off = 16; off; off >>= 1) sum += __shfl_down_sync(0xffffffffu, sum, off);
        if (lane == 0) SIM[(b*TT + t)*WN + w] = sum;
    }
}

// two-pass chunked exclusive cumsum over t
__global__ void cumsum_part_kernel(const float* __restrict__ V, float* __restrict__ PARTS){
    int c = threadIdx.x;
    int chunk = blockIdx.x;
    int b = blockIdx.y;
    float s = 0.f;
    const float* p = &V[((b*TT) + (chunk << 6))*CC + c];
#pragma unroll 8
    for (int u = 0; u < 64; u++) s += p[u*CC];
    PARTS[(b*8 + chunk)*CC + c] = s;
}

__global__ void cumsum_write_kernel(const float* __restrict__ V, const float* __restrict__ PARTS,
                                    float* __restrict__ CUM){
    int c = threadIdx.x;
    int chunk = blockIdx.x;
    int b = blockIdx.y;
    float base = 0.f;
    for (int j = 0; j < chunk; j++) base += PARTS[(b*8 + j)*CC + c];
    int t0 = chunk << 6;
    const float* vp = &V[((b*TT) + t0)*CC + c];
    float* cp = &CUM[((b*(TT+1)) + t0)*CC + c];
    float acc = base;
#pragma unroll 8
    for (int u = 0; u < 64; u++){
        cp[u*CC] = acc;
        acc += vp[u*CC];
    }
    if (chunk == 7) cp[64*CC] = acc;
}

// fused labels (warp-0 argmax) + split-A row build; ONE window per launch
__global__ void labelbuild_kernel(const float* __restrict__ SIM, const float* __restrict__ CUM,
                                  const float* __restrict__ EP,
                                  __half* __restrict__ Aho, __half* __restrict__ Alo,
                                  int nt0, int s){
    int row = blockIdx.x;                      // 0..BB*nt0-1
    int b = row / nt0, t0 = row % nt0;
    __shared__ int slab;
    int tid = threadIdx.x;                     // 512
    if (tid < 32){
        const float* sp = &SIM[(b*TT + t0)*WN + tid];
        float sum = 0.f;
        for (int u = 0; u < s; u++) sum += sp[u*WN];
        float best = sum; int bi = tid;
#pragma unroll
        for (int off = 16; off; off >>= 1){
            float ov = __shfl_down_sync(0xffffffffu, best, off);
            int   oi = __shfl_down_sync(0xffffffffu, bi,   off);
            if (ov > best || (ov == best && oi < bi)){ best = ov; bi = oi; }
        }
        if (tid == 0) slab = bi;
    }
    __syncthreads();
    int lab = slab;
    int c = tid;
    float vu = (CUM[(b*(TT+1) + t0 + s)*CC + c] - CUM[(b*(TT+1) + t0)*CC + c]) * (1.f/(float)s);
    float v = vu * EP[(b*WN + lab)*(2*CC) + CC + c];
    __half h, l; split_h(v, h, l);
    Aho[(long)row*CC + c] = h;
    Alo[(long)row*CC + c] = l;
}

// adaptive max pool over valid prefix; ONE window per launch
__global__ void pool_kernel(const int* __restrict__ vid_len, const float* __restrict__ Mw,
                            float* __restrict__ PO, int nt0, int s){
    int i = blockIdx.x, b = blockIdx.y;
    int d = threadIdx.x;
    int Lin = vid_len[b] * 8;
    if (Lin < 1) Lin = 1;
    int start = (i * Lin) >> 6;
    int end   = ((i + 1) * Lin + 63) >> 6;
    const float* base = Mw + (long)b*nt0*DD + d;
    float m = -3.402823466e38f;
    for (int r = start; r < end; r++){
        int t0 = (r >> 3) + (r & 7) * s;
        float v = base[(long)t0*DD];
        m = fmaxf(m, v);
    }
    PO[(b*PP + i)*DD + d] = m;
}

// seg head, ONE window per launch
__global__ void seg_kernel(const float* __restrict__ PO, const float* __restrict__ sw,
                           const float* __restrict__ sb, float* __restrict__ out, int base){
    int p = blockIdx.x, b = blockIdx.y;
    int tid = threadIdx.x;
    const float* pp = &PO[(b*PP + p)*DD];
    float a0 = 0.f, a1 = 0.f;
    for (int d = tid; d < DD; d += 128){
        float v = pp[d];
        a0 = fmaf(v, sw[2*d],     a0);
        a1 = fmaf(v, sw[2*d + 1], a1);
    }
#pragma unroll
    for (int off = 16; off; off >>= 1){
        a0 += __shfl_down_sync(0xffffffffu, a0, off);
        a1 += __shfl_down_sync(0xffffffffu, a1, off);
    }
    __shared__ float s0[4], s1[4];
    if ((tid & 31) == 0){ s0[tid >> 5] = a0; s1[tid >> 5] = a1; }
    __syncthreads();
    if (tid == 0){
        float r0 = s0[0] + s0[1] + s0[2] + s0[3];
        float r1 = s1[0] + s1[1] + s1[2] + s1[3];
        out[base + b*128 + p]       = r0 + sb[0];
        out[base + b*128 + 64 + p]  = r1 + sb[1];
    }
}

// st/en heads: ONE window (2 matrices) per launch; matbase selects PART section
#define KSPLIT 64
__global__ void vechead_partial(const float* __restrict__ Wst, const float* __restrict__ Wen,
                                const float* __restrict__ PO, float* __restrict__ PART,
                                int matbase){
    int ks = blockIdx.x;
    const float* W = blockIdx.y ? Wen : Wst;
    int mat = matbase + blockIdx.y;
    int wid = threadIdx.x >> 5, lane = threadIdx.x & 31;
    float acc[4][2] = {{0.f,0.f},{0.f,0.f},{0.f,0.f},{0.f,0.f}};
    int kbase = ks * 512;
    for (int kk = wid; kk < 512; kk += 8){
        int k = kbase + kk;
        float w0 = W[k*64 + lane];
        float w1 = W[k*64 + 32 + lane];
        int p = k & 63, d = k >> 6;
#pragma unroll
        for (int b = 0; b < 4; b++){
            float v = PO[(b*PP + p)*DD + d];
            acc[b][0] = fmaf(v, w0, acc[b][0]);
            acc[b][1] = fmaf(v, w1, acc[b][1]);
        }
    }
    __shared__ float red[8][4][64];
#pragma unroll
    for (int b = 0; b < 4; b++){
        red[wid][b][lane]      = acc[b][0];
        red[wid][b][lane + 32] = acc[b][1];
    }
    __syncthreads();
    int o = threadIdx.x;
    int b = o >> 6, p = o & 63;
    float s = 0.f;
#pragma unroll
    for (int w = 0; w < 8; w++) s += red[w][b][p];
    PART[((mat*KSPLIT + ks)*4 + b)*64 + p] = s;
}

__global__ void vechead_final(const float* __restrict__ PART,
                              const float* __restrict__ b0, const float* __restrict__ b1,
                              const float* __restrict__ b2, const float* __restrict__ b3,
                              float* __restrict__ out){
    int o = blockIdx.x * 256 + threadIdx.x;
    if (o >= 4*4*64) return;
    int mat = o >> 8, rem = o & 255;
    int b = rem >> 6, p = rem & 63;
    float s = 0.f;
#pragma unroll
    for (int ks = 0; ks < KSPLIT; ks++) s += PART[((mat*KSPLIT + ks)*4 + b)*64 + p];
    const float* bias = (mat == 0) ? b0 : (mat == 1) ? b1 : (mat == 2) ? b2 : b3;
    int off = (mat == 0) ? 512 : (mat == 1) ? 768 : (mat == 2) ? 1536 : 1792;
    out[off + b*64 + p] = s + bias[p];
}

// ---------------- launcher ----------------
extern "C" void kernel_launch(void* const* d_in, const int* in_sizes, int n_in,
                              void* d_out, int out_size){
    const float* vis     = (const float*)d_in[0];
    const float* qry     = (const float*)d_in[1];
    const int*   vlen    = (const int*)  d_in[2];
    const float* vid_w1  = (const float*)d_in[3];
    const float* vid_b1  = (const float*)d_in[4];
    const float* vid_w2  = (const float*)d_in[5];
    const float* vid_b2  = (const float*)d_in[6];
    const float* s1_w1   = (const float*)d_in[7];
    const float* s1_b1   = (const float*)d_in[8];
    const float* s1_w2   = (const float*)d_in[9];
    const float* s1_b2   = (const float*)d_in[10];
    const float* s2_w1   = (const float*)d_in[11];
    const float* s2_b1   = (const float*)d_in[12];
    const float* s2_w2   = (const float*)d_in[13];
    const float* s2_b2   = (const float*)d_in[14];
    const float* proj_w  = (const float*)d_in[15];
    const float* proj_b  = (const float*)d_in[16];
    const float* st_w0   = (const float*)d_in[17];
    const float* st_b0   = (const float*)d_in[18];
    const float* en_w0   = (const float*)d_in[19];
    const float* en_b0   = (const float*)d_in[20];
    const float* sg_w0   = (const float*)d_in[21];
    const float* sg_b0   = (const float*)d_in[22];
    const float* st_w1   = (const float*)d_in[23];
    const float* st_b1   = (const float*)d_in[24];
    const float* en_w1   = (const float*)d_in[25];
    const float* en_b1   = (const float*)d_in[26];
    const float* sg_w1   = (const float*)d_in[27];
    const float* sg_b1   = (const float*)d_in[28];
    float* out = (float*)d_out;

    __half *Xvh, *Xvl, *Hh, *Hl, *Xqh, *Xql, *Hqh, *Hql, *Ah, *Al;
    __half *w1h, *w1l, *w2h, *w2l, *pwh, *pwl, *wq1h, *wq1l, *wq2h, *wq2l;
    float *V, *EP, *SIM, *CUM, *PARTS, *Md, *POOL, *PART, *BQ1, *BQ2;
    cudaGetSymbolAddress((void**)&Xvh, g_Xvh);
    cudaGetSymbolAddress((void**)&Xvl, g_Xvl);
    cudaGetSymbolAddress((void**)&Hh,  g_Hh);
    cudaGetSymbolAddress((void**)&Hl,  g_Hl);
    cudaGetSymbolAddress((void**)&V,   g_V);
    cudaGetSymbolAddress((void**)&Xqh, g_Xqh);
    cudaGetSymbolAddress((void**)&Xql, g_Xql);
    cudaGetSymbolAddress((void**)&Hqh, g_Hqh);
    cudaGetSymbolAddress((void**)&Hql, g_Hql);
    cudaGetSymbolAddress((void**)&EP,  g_ep);
    cudaGetSymbolAddress((void**)&SIM, g_sim);
    cudaGetSymbolAddress((void**)&CUM, g_cum);
    cudaGetSymbolAddress((void**)&PARTS, g_parts);
    cudaGetSymbolAddress((void**)&Ah,  g_Ah);
    cudaGetSymbolAddress((void**)&Al,  g_Al);
    cudaGetSymbolAddress((void**)&Md,  g_Md);
    cudaGetSymbolAddress((void**)&POOL,g_pool);
    cudaGetSymbolAddress((void**)&PART,g_part);
    cudaGetSymbolAddress((void**)&w1h, g_w1h);
    cudaGetSymbolAddress((void**)&w1l, g_w1l);
    cudaGetSymbolAddress((void**)&w2h, g_w2h);
    cudaGetSymbolAddress((void**)&w2l, g_w2l);
    cudaGetSymbolAddress((void**)&pwh, g_pwh);
    cudaGetSymbolAddress((void**)&pwl, g_pwl);
    cudaGetSymbolAddress((void**)&wq1h, g_wq1h);
    cudaGetSymbolAddress((void**)&wq1l, g_wq1l);
    cudaGetSymbolAddress((void**)&wq2h, g_wq2h);
    cudaGetSymbolAddress((void**)&wq2l, g_wq2l);
    cudaGetSymbolAddress((void**)&BQ1, g_bq1);
    cudaGetSymbolAddress((void**)&BQ2, g_bq2);

    cudaFuncSetAttribute(gemm_mma<1,0,1>, cudaFuncAttributeMaxDynamicSharedMemorySize, GM_SMEM);
    cudaFuncSetAttribute(gemm_mma<0,1,0>, cudaFuncAttributeMaxDynamicSharedMemorySize, GM_SMEM);

    // one-time aux stream + events (resources only; work is identical each call)
    static cudaStream_t aux = nullptr;
    static cudaEvent_t evF, evT, evPE, evV, evS, evC, evL1, evP0, evH0;
    if (aux == nullptr){
        cudaStreamCreateWithFlags(&aux, cudaStreamNonBlocking);
        cudaEventCreateWithFlags(&evF,  cudaEventDisableTiming);
        cudaEventCreateWithFlags(&evT,  cudaEventDisableTiming);
        cudaEventCreateWithFlags(&evPE, cudaEventDisableTiming);
        cudaEventCreateWithFlags(&evV,  cudaEventDisableTiming);
        cudaEventCreateWithFlags(&evS,  cudaEventDisableTiming);
        cudaEventCreateWithFlags(&evC,  cudaEventDisableTiming);
        cudaEventCreateWithFlags(&evL1, cudaEventDisableTiming);
        cudaEventCreateWithFlags(&evP0, cudaEventDisableTiming);
        cudaEventCreateWithFlags(&evH0, cudaEventDisableTiming);
    }

    const int NSW_NONE = 1 << 30;

    // ---- fork at top ----
    cudaEventRecord(evF, 0);
    cudaStreamWaitEvent(aux, evF, 0);

    // aux: weight transposes + bias packs (overlaps PE-add on main)
    TSArgs ts;
    ts.src[0] = vid_w1; ts.dh[0] = w1h;  ts.dl[0] = w1l;
    ts.src[1] = vid_w2; ts.dh[1] = w2h;  ts.dl[1] = w2l;
    ts.src[2] = proj_w; ts.dh[2] = pwh;  ts.dl[2] = pwl;
    ts.src[3] = s1_w1;  ts.dh[3] = wq1h;           ts.dl[3] = wq1l;
    ts.src[4] = s2_w1;  ts.dh[4] = wq1h + 512*512; ts.dl[4] = wq1l + 512*512;
    ts.src[5] = s1_w2;  ts.dh[5] = wq2h;           ts.dl[5] = wq2l;
    ts.src[6] = s2_w2;  ts.dh[6] = wq2h + 512*512; ts.dl[6] = wq2l + 512*512;
    transpose_split_all<<<dim3(16,16,7), dim3(32,8), 0, aux>>>(ts);
    pack_biases<<<4, 512, 0, aux>>>(s1_b1, s2_b1, s1_b2, s2_b2, BQ1, BQ2);
    cudaEventRecord(evT, aux);

    // main: PE add + split (vis & query)
    add_pe_split_all<<<BB*TT + BB*WN, CC>>>(vis, Xvh, Xvl, qry, Xqh, Xql);
    cudaEventRecord(evPE, 0);
    cudaStreamWaitEvent(0, evT, 0);            // weights ready for vid GEMMs

    // aux: enc chain (needs Xq from PE + its weights, both now on aux timeline)
    cudaStreamWaitEvent(aux, evPE, 0);
    gemm_mma<1,0,1><<<dim3(2*CC/64, BB*WN/64), 128, GM_SMEM, aux>>>(
        Xqh, Xql, wq1h, wq1l, BQ1, nullptr, Hqh, Hql, BB*WN, 2*CC, CC, CC, CC, NSW_NONE, 0);
    gemm_mma<0,1,0><<<dim3(2*CC/64, BB*WN/64), 128, GM_SMEM, aux>>>(
        Hqh, Hql, wq2h, wq2l, BQ2, EP, nullptr, nullptr, BB*WN, 2*CC, CC, 2*CC, CC, CC, CC);

    // main: vid MLP
    gemm_mma<1,0,1><<<dim3(CC/64, BB*TT/64), 128, GM_SMEM>>>(
        Xvh, Xvl, w1h, w1l, vid_b1, nullptr, Hh, Hl, BB*TT, CC, CC, CC, CC, NSW_NONE, 0);
    gemm_mma<0,1,0><<<dim3(CC/64, BB*TT/64), 128, GM_SMEM>>>(
        Hh, Hl, w2h, w2l, vid_b2, V, nullptr, nullptr, BB*TT, CC, CC, CC, CC, NSW_NONE, 0);
    cudaEventRecord(evV, 0);                   // V ready

    // aux: sim (needs V + EP), concurrent with cumsum on main
    cudaStreamWaitEvent(aux, evV, 0);
    sim_kernel<<<dim3(TT, BB), 256, 0, aux>>>(V, EP, SIM);
    cudaEventRecord(evS, aux);

    // main: chunked prefix sums of v
    cumsum_part_kernel<<<dim3(8, BB), 512>>>(V, PARTS);
    cumsum_write_kernel<<<dim3(8, BB), 512>>>(V, PARTS, CUM);
    cudaEventRecord(evC, 0);

    // aux: labelbuild window 1 (needs SIM + CUM); concurrent with w0 path on main
    cudaStreamWaitEvent(aux, evC, 0);
    labelbuild_kernel<<<ROWS1, CC, 0, aux>>>(SIM, CUM, EP,
        Ah + (long)AOFF1*CC, Al + (long)AOFF1*CC, NT0_W1, 16);
    cudaEventRecord(evL1, aux);

    // main: labelbuild window 0 -> proj window 0
    cudaStreamWaitEvent(0, evS, 0);
    labelbuild_kernel<<<ROWS0, CC>>>(SIM, CUM, EP, Ah, Al, NT0_W0, 8);
    gemm_mma<0,1,0><<<dim3(DD/64, 2048/64), 128, GM_SMEM>>>(
        Ah, Al, pwh, pwl, proj_b, Md, nullptr, nullptr, 2048, DD, CC, CC, CC, NSW_NONE, 0);
    cudaEventRecord(evP0, 0);

    // aux: window-0 tail (pool, seg, vechead) under proj window 1
    cudaStreamWaitEvent(aux, evP0, 0);
    pool_kernel<<<dim3(PP, BB), DD, 0, aux>>>(vlen, Md, POOL, NT0_W0, 8);
    seg_kernel<<<dim3(PP, BB), 128, 0, aux>>>(POOL, sg_w0, sg_b0, out, 0);
    vechead_partial<<<dim3(KSPLIT, 2), 256, 0, aux>>>(st_w0, en_w0, POOL, PART, 0);
    cudaEventRecord(evH0, aux);

    // main: proj window 1 -> window-1 tail
    cudaStreamWaitEvent(0, evL1, 0);
    gemm_mma<0,1,0><<<dim3(DD/64, 2048/64), 128, GM_SMEM>>>(
        Ah + (long)AOFF1*CC, Al + (long)AOFF1*CC, pwh, pwl, proj_b,
        Md + (long)AOFF1*DD, nullptr, nullptr, 2048, DD, CC, CC, CC, NSW_NONE, 0);
    pool_kernel<<<dim3(PP, BB), DD>>>(vlen, Md + (long)AOFF1*DD, POOL + (long)BB*PP*DD, NT0_W1, 16);
    seg_kernel<<<dim3(PP, BB), 128>>>(POOL + (long)BB*PP*DD, sg_w1, sg_b1, out, 1024);
    vechead_partial<<<dim3(KSPLIT, 2), 256>>>(st_w1, en_w1, POOL + (long)BB*PP*DD, PART, 2);

    // ---- join + final ----
    cudaStreamWaitEvent(0, evH0, 0);
    vechead_final<<<4, 256>>>(PART, st_b0, en_b0, st_b1, en_b1, out);
}

// round 13
// speedup vs baseline: 1.1720x; 1.1720x over previous
#include <cuda_runtime.h>
#include <cuda_fp16.h>
#include <math.h>
#include <stdint.h>

// Problem constants (fixed shapes)
#define BB 4
#define TT 512
#define CC 512
#define WN 32
#define DD 512
#define PP 64

#define NT0_W0 (TT-8+1)          // 505
#define NT0_W1 (TT-16+1)         // 497
#define ROWS0 (BB*NT0_W0)        // 2020
#define ROWS1 (BB*NT0_W1)        // 1988
#define AOFF1 2048               // window-1 A/Md row offset (pad rows stay zero)

// ---------------- scratch (static device globals; no allocation) ----------------
__device__ __half g_Xvh[BB*TT*CC], g_Xvl[BB*TT*CC];
__device__ __half g_Hh [BB*TT*CC], g_Hl [BB*TT*CC];
__device__ float g_V  [BB*TT*CC];
__device__ __half g_Xqh[BB*WN*CC], g_Xql[BB*WN*CC];
__device__ __half g_Hqh[BB*WN*2*CC], g_Hql[BB*WN*2*CC];   // [128, 1024]
__device__ float g_ep [BB*WN*2*CC];                        // [128, 1024] = [E1 | E2]
__device__ float g_sim[BB*TT*WN];
__device__ float g_cum[BB*(TT+1)*CC];
__device__ float g_parts[BB*8*CC];
__device__ __half g_Ah[4096*CC], g_Al[4096*CC];   // zero-init; pad rows never written
__device__ float g_Md [4096*DD];
__device__ float g_pool[2*BB*PP*DD];               // per-window buffers
__device__ float g_part[4*64*BB*PP];
__device__ __half g_w1h[CC*CC],   g_w1l[CC*CC];    // vid_w1^T
__device__ __half g_w2h[CC*CC],   g_w2l[CC*CC];    // vid_w2^T
__device__ __half g_pwh[CC*DD],   g_pwl[CC*DD];    // proj_w^T
__device__ __half g_wq1h[2*CC*CC],g_wq1l[2*CC*CC]; // [s1_w1^T ; s2_w1^T]
__device__ __half g_wq2h[2*CC*CC],g_wq2l[2*CC*CC]; // [s1_w2^T ; s2_w2^T]
__device__ float g_bq1[2*CC];                       // [s1_b1 ; s2_b1]
__device__ float g_bq2[2*CC];                       // [s1_b2 ; s2_b2]

static inline int cdiv(int a, int b){ return (a + b - 1) / b; }

// ---------------- mma.sync helpers (sm_80+ path; legal on plain sm_100) ----------------
__device__ __forceinline__ uint32_t smem_to_u32(const void* p) {
    uint32_t a;
    asm("{ .reg .u64 tmp; cvta.to.shared.u64 tmp, %1; cvt.u32.u64 %0, tmp; }" : "=r"(a) : "l"(p));
    return a;
}
__device__ __forceinline__ void ldmx4(uint32_t* r, uint32_t addr){
    asm volatile("ldmatrix.sync.aligned.m8n8.x4.shared.b16 {%0,%1,%2,%3}, [%4];"
        : "=r"(r[0]),"=r"(r[1]),"=r"(r[2]),"=r"(r[3]) : "r"(addr));
}
__device__ __forceinline__ void mma16816(float* c, const uint32_t* a, uint32_t b0, uint32_t b1){
    asm volatile("mma.sync.aligned.m16n8k16.row.col.f32.f16.f16.f32 "
        "{%0,%1,%2,%3}, {%4,%5,%6,%7}, {%8,%9}, {%0,%1,%2,%3};"
        : "+f"(c[0]),"+f"(c[1]),"+f"(c[2]),"+f"(c[3])
        : "r"(a[0]),"r"(a[1]),"r"(a[2]),"r"(a[3]), "r"(b0),"r"(b1));
}
__device__ __forceinline__ void cp_async16(uint32_t saddr, const void* gaddr){
    asm volatile("cp.async.cg.shared.global [%0], [%1], 16;" :: "r"(saddr), "l"(gaddr));
}
// fp16 hi/lo split: hi+lo captures ~22 mantissa bits of v
__device__ __forceinline__ void split_h(float v, __half& h, __half& l){
    h = __float2half_rn(v);
    l = __float2half_rn(v - __half2float(h));
}

// ---------- tensor-core fp16-split GEMM: C = (Ah+Al)@(Bh+Bl)^T, 3 products ----------
// Block tile 64x64, 4 warps (2m x 2n), warp tile 32x32, K-chunk 32.
// 3-stage smem pipeline + fragment double-buffer. 4 CTAs/SM (128 threads).
// If n0 >= nswitch, A pointers shift by aoff elements (fuses two GEMMs along N).
#define GM_STG 16384
#define GM_SMEM (3*16384)

template<int RELU, int WF, int WS>
__global__ void __launch_bounds__(128, 4)
gemm_mma(const __half* __restrict__ Ah, const __half* __restrict__ Al,
         const __half* __restrict__ Bh, const __half* __restrict__ Bl,
         const float* __restrict__ bias, float* __restrict__ outF,
         __half* __restrict__ outH, __half* __restrict__ outL,
         int M, int N, int K, int lda, int ldb, int nswitch, int aoff)
{
    extern __shared__ char smem[];
    uint32_t sbase = smem_to_u32(smem);
    int tid = threadIdx.x;
    int warp = tid >> 5, lane = tid & 31;
    int wm = warp & 1, wn = warp >> 1;          // 2m x 2n warps
    int m0 = blockIdx.y << 6, n0 = blockIdx.x << 6;
    if (n0 >= nswitch){ Ah += aoff; Al += aoff; }

    float acc[2][4][4];
#pragma unroll
    for (int a = 0; a < 2; a++)
#pragma unroll
        for (int b = 0; b < 4; b++)
#pragma unroll
            for (int c = 0; c < 4; c++) acc[a][b][c] = 0.f;

    int nch = K >> 5;

    auto load_chunk = [&](int ch){
        int stage = ch % 3;
        int k0 = ch << 5;
#pragma unroll
        for (int j = 0; j < 8; j++){
            int i = tid + (j << 7);             // 0..1023
            int tile = i >> 8;                  // 0:Ah 1:Al 2:Bh 3:Bl
            int rem = i & 255;
            int g = rem >> 6, r = rem & 63;
            const __half* gp;
            if (tile < 2) gp = (tile ? Al : Ah) + (long)(m0 + r)*lda + k0 + (g << 3);
            else          gp = ((tile & 1) ? Bl : Bh) + (long)(n0 + r)*ldb + k0 + (g << 3);
            uint32_t sa = sbase + stage*GM_STG + (tile << 12) + (g << 10) + (r << 4);
            cp_async16(sa, gp);
        }
        asm volatile("cp.async.commit_group;");
    };

    load_chunk(0);
    if (nch > 1) load_chunk(1);

    int ra = lane & 15;
    int ghalf = lane >> 4;

    for (int ch = 0; ch < nch; ch++){
        if (ch + 1 < nch) asm volatile("cp.async.wait_group 1;");
        else              asm volatile("cp.async.wait_group 0;");
        __syncthreads();
        if (ch + 2 < nch) load_chunk(ch + 2);

        uint32_t st = sbase + (ch % 3)*GM_STG;

        uint32_t a_h[2][2][4], a_l[2][2][4], b_h[2][2][4], b_l[2][2][4];

        auto load_frag = [&](int ks, int buf){
            int ga = (ks << 1) + ghalf;
#pragma unroll
            for (int mt = 0; mt < 2; mt++){
                int r = (wm << 5) + (mt << 4) + ra;
                uint32_t off = (uint32_t)((ga << 10) + (r << 4));
                ldmx4(a_h[buf][mt], st + off);
                ldmx4(a_l[buf][mt], st + 4096 + off);
            }
#pragma unroll
            for (int np = 0; np < 2; np++){
                int r = (wn << 5) + (np << 4) + ra;
                uint32_t off = (uint32_t)((ga << 10) + (r << 4));
                ldmx4(b_h[buf][np], st + 8192  + off);
                ldmx4(b_l[buf][np], st + 12288 + off);
            }
        };

        load_frag(0, 0);
#pragma unroll
        for (int ks = 0; ks < 2; ks++){
            int buf = ks & 1;
            if (ks == 0) load_frag(1, 1);
#pragma unroll
            for (int mt = 0; mt < 2; mt++)
#pragma unroll
                for (int nt = 0; nt < 4; nt++){
                    int np = nt >> 1, pr = nt & 1;
                    mma16816(acc[mt][nt], a_h[buf][mt], b_h[buf][np][pr], b_h[buf][np][pr+2]);
                    mma16816(acc[mt][nt], a_h[buf][mt], b_l[buf][np][pr], b_l[buf][np][pr+2]);
                    mma16816(acc[mt][nt], a_l[buf][mt], b_h[buf][np][pr], b_h[buf][np][pr+2]);
                }
        }
    }
    __syncthreads();

    // epilogue
    int col_base = n0 + (wn << 5);
    int r0 = lane >> 2;
    int cp2 = (lane & 3) << 1;
#pragma unroll
    for (int mt = 0; mt < 2; mt++){
        int row_base = m0 + (wm << 5) + (mt << 4);
#pragma unroll
        for (int i = 0; i < 2; i++){
            int m = row_base + r0 + (i << 3);
#pragma unroll
            for (int nt = 0; nt < 4; nt++){
                int col = col_base + (nt << 3) + cp2;
                float v0 = acc[mt][nt][i*2+0] + bias[col];
                float v1 = acc[mt][nt][i*2+1] + bias[col+1];
                if (RELU){ v0 = fmaxf(v0, 0.f); v1 = fmaxf(v1, 0.f); }
                if (WF){
                    float2 o; o.x = v0; o.y = v1;
                    *(float2*)&outF[(long)m*N + col] = o;
                }
                if (WS){
                    __half h0, l0, h1, l1;
                    split_h(v0, h0, l0);
                    split_h(v1, h1, l1);
                    *(__half2*)&outH[(long)m*N + col] = __halves2half2(h0, h1);
                    *(__half2*)&outL[(long)m*N + col] = __halves2half2(l0, l1);
                }
            }
        }
    }
}

// ---------------- small kernels ----------------

// PE add + fp16 split for vis (rows < 2048) and query (rows >= 2048)
__global__ void add_pe_split_all(const float* __restrict__ xv,
                                 __half* __restrict__ xvh, __half* __restrict__ xvl,
                                 const float* __restrict__ xq,
                                 __half* __restrict__ xqh, __half* __restrict__ xql){
    int row = blockIdx.x;
    int c = threadIdx.x;
    const float* x; __half *yh, *yl; int t;
    if (row < BB*TT){ x = xv; yh = xvh; yl = xvl; t = row % TT; }
    else { row -= BB*TT; x = xq; yh = xqh; yl = xql; t = row % WN; }
    int i2 = (c >> 1) << 1;
    float ang = (float)t * expf((float)i2 * -1.7988946039352293e-2f);
    float pe = (c & 1) ? cosf(ang) : sinf(ang);
    float v = x[row*CC + c] + pe;
    __half h, l; split_h(v, h, l);
    yh[row*CC + c] = h; yl[row*CC + c] = l;
}

// batched 512x512 transpose+split: z selects matrix
struct TSArgs { const float* src[7]; __half* dh[7]; __half* dl[7]; };
__global__ void transpose_split_all(TSArgs a){
    int z = blockIdx.z;
    const float* W = a.src[z];
    __half* Th = a.dh[z];
    __half* Tl = a.dl[z];
    __shared__ float t[32][33];
    int bx = blockIdx.x << 5, by = blockIdx.y << 5;
    int x = threadIdx.x, y = threadIdx.y;
#pragma unroll
    for (int i = 0; i < 32; i += 8) t[y+i][x] = W[(long)(by + y + i)*512 + bx + x];
    __syncthreads();
#pragma unroll
    for (int i = 0; i < 32; i += 8){
        float v = t[x][y+i];
        __half h, l; split_h(v, h, l);
        long o = (long)(bx + y + i)*512 + by + x;
        Th[o] = h; Tl[o] = l;
    }
}

// pack both fused biases in one launch (4 blocks x 512)
__global__ void pack_biases(const float* __restrict__ a1, const float* __restrict__ a2,
                            const float* __restrict__ b1, const float* __restrict__ b2,
                            float* __restrict__ dq1, float* __restrict__ dq2){
    int blk = blockIdx.x;
    int i = threadIdx.x;
    if (blk == 0) dq1[i] = a1[i];
    else if (blk == 1) dq1[512 + i] = a2[i];
    else if (blk == 2) dq2[i] = b1[i];
    else dq2[512 + i] = b2[i];
}

// sim[b, t, w] = dot(v[b,t,:], E1[b,w,:]); E1 = EP[:, 0:512] with row stride 1024
__global__ void sim_kernel(const float* __restrict__ V, const float* __restrict__ EP,
                           float* __restrict__ SIM){
    int t = blockIdx.x, b = blockIdx.y;
    __shared__ float vrow[CC];
    int tid = threadIdx.x;
    const float* vp = &V[(b*TT + t)*CC];
    vrow[tid]       = vp[tid];
    vrow[tid + 256] = vp[tid + 256];
    __syncthreads();
    int wid = tid >> 5, lane = tid & 31;
    for (int w = wid; w < WN; w += 8){
        const float* e = &EP[(b*WN + w)*(2*CC)];
        float sum = 0.f;
        for (int c = lane; c < CC; c += 32) sum = fmaf(vrow[c], e[c], sum);
#pragma unroll
        for (int off = 16; off; off >>= 1) sum += __shfl_down_sync(0xffffffffu, sum, off);
        if (lane == 0) SIM[(b*TT + t)*WN + w] = sum;
    }
}

// two-pass chunked exclusive cumsum over t
__global__ void cumsum_part_kernel(const float* __restrict__ V, float* __restrict__ PARTS){
    int c = threadIdx.x;
    int chunk = blockIdx.x;
    int b = blockIdx.y;
    float s = 0.f;
    const float* p = &V[((b*TT) + (chunk << 6))*CC + c];
#pragma unroll 8
    for (int u = 0; u < 64; u++) s += p[u*CC];
    PARTS[(b*8 + chunk)*CC + c] = s;
}

__global__ void cumsum_write_kernel(const float* __restrict__ V, const float* __restrict__ PARTS,
                                    float* __restrict__ CUM){
    int c = threadIdx.x;
    int chunk = blockIdx.x;
    int b = blockIdx.y;
    float base = 0.f;
    for (int j = 0; j < chunk; j++) base += PARTS[(b*8 + j)*CC + c];
    int t0 = chunk << 6;
    const float* vp = &V[((b*TT) + t0)*CC + c];
    float* cp = &CUM[((b*(TT+1)) + t0)*CC + c];
    float acc = base;
#pragma unroll 8
    for (int u = 0; u < 64; u++){
        cp[u*CC] = acc;
        acc += vp[u*CC];
    }
    if (chunk == 7) cp[64*CC] = acc;
}

// fused labels (warp-0 argmax) + split-A row build; ONE window per launch
__global__ void labelbuild_kernel(const float* __restrict__ SIM, const float* __restrict__ CUM,
                                  const float* __restrict__ EP,
                                  __half* __restrict__ Aho, __half* __restrict__ Alo,
                                  int nt0, int s){
    int row = blockIdx.x;                      // 0..BB*nt0-1
    int b = row / nt0, t0 = row % nt0;
    __shared__ int slab;
    int tid = threadIdx.x;                     // 512
    if (tid < 32){
        const float* sp = &SIM[(b*TT + t0)*WN + tid];
        float sum = 0.f;
        for (int u = 0; u < s; u++) sum += sp[u*WN];
        float best = sum; int bi = tid;
#pragma unroll
        for (int off = 16; off; off >>= 1){
            float ov = __shfl_down_sync(0xffffffffu, best, off);
            int   oi = __shfl_down_sync(0xffffffffu, bi,   off);
            if (ov > best || (ov == best && oi < bi)){ best = ov; bi = oi; }
        }
        if (tid == 0) slab = bi;
    }
    __syncthreads();
    int lab = slab;
    int c = tid;
    float vu = (CUM[(b*(TT+1) + t0 + s)*CC + c] - CUM[(b*(TT+1) + t0)*CC + c]) * (1.f/(float)s);
    float v = vu * EP[(b*WN + lab)*(2*CC) + CC + c];
    __half h, l; split_h(v, h, l);
    Aho[(long)row*CC + c] = h;
    Alo[(long)row*CC + c] = l;
}

// adaptive max pool over valid prefix; z = window (Md rows at 0 / AOFF1)
__global__ void pool_kernel(const int* __restrict__ vid_len, const float* __restrict__ Md,
                            float* __restrict__ POOL){
    int i = blockIdx.x, b = blockIdx.y, z = blockIdx.z;
    int d = threadIdx.x;
    int s   = z ? 16 : 8;
    int nt0 = TT - s + 1;
    const float* Mw = Md + (long)(z ? AOFF1 : 0)*DD;
    float* PO = POOL + (long)z*BB*PP*DD;
    int Lin = vid_len[b] * 8;
    if (Lin < 1) Lin = 1;
    int start = (i * Lin) >> 6;
    int end   = ((i + 1) * Lin + 63) >> 6;
    const float* base = Mw + (long)b*nt0*DD + d;
    float m = -3.402823466e38f;
    for (int r = start; r < end; r++){
        int t0 = (r >> 3) + (r & 7) * s;
        float v = base[(long)t0*DD];
        m = fmaxf(m, v);
    }
    PO[(b*PP + i)*DD + d] = m;
}

// seg head, both windows (z)
struct SegArgs { const float* sw[2]; const float* sb[2]; };
__global__ void seg_kernel(SegArgs a, const float* __restrict__ POOL, float* __restrict__ out){
    int p = blockIdx.x, b = blockIdx.y, z = blockIdx.z;
    const float* sw = a.sw[z];
    const float* sb = a.sb[z];
    const float* PO = POOL + (long)z*BB*PP*DD;
    int base = z ? 1024 : 0;
    int tid = threadIdx.x;
    const float* pp = &PO[(b*PP + p)*DD];
    float a0 = 0.f, a1 = 0.f;
    for (int d = tid; d < DD; d += 128){
        float v = pp[d];
        a0 = fmaf(v, sw[2*d],     a0);
        a1 = fmaf(v, sw[2*d + 1], a1);
    }
#pragma unroll
    for (int off = 16; off; off >>= 1){
        a0 += __shfl_down_sync(0xffffffffu, a0, off);
        a1 += __shfl_down_sync(0xffffffffu, a1, off);
    }
    __shared__ float s0[4], s1[4];
    if ((tid & 31) == 0){ s0[tid >> 5] = a0; s1[tid >> 5] = a1; }
    __syncthreads();
    if (tid == 0){
        float r0 = s0[0] + s0[1] + s0[2] + s0[3];
        float r1 = s1[0] + s1[1] + s1[2] + s1[3];
        out[base + b*128 + p]       = r0 + sb[0];
        out[base + b*128 + 64 + p]  = r1 + sb[1];
    }
}

// st/en heads: 4 matrices x 64 k-splits in one launch
#define KSPLIT 64
struct VHArgs { const float* W[4]; };
__global__ void vechead_partial(VHArgs a, const float* __restrict__ POOL,
                                float* __restrict__ PART){
    int ks = blockIdx.x;
    int mat = blockIdx.y;                      // 0=st0 1=en0 2=st1 3=en1
    const float* W = a.W[mat];
    const float* PO = POOL + (long)(mat >> 1)*BB*PP*DD;
    int wid = threadIdx.x >> 5, lane = threadIdx.x & 31;
    float acc[4][2] = {{0.f,0.f},{0.f,0.f},{0.f,0.f},{0.f,0.f}};
    int kbase = ks * 512;
    for (int kk = wid; kk < 512; kk += 8){
        int k = kbase + kk;
        float w0 = W[k*64 + lane];
        float w1 = W[k*64 + 32 + lane];
        int p = k & 63, d = k >> 6;
#pragma unroll
        for (int b = 0; b < 4; b++){
            float v = PO[(b*PP + p)*DD + d];
            acc[b][0] = fmaf(v, w0, acc[b][0]);
            acc[b][1] = fmaf(v, w1, acc[b][1]);
        }
    }
    __shared__ float red[8][4][64];
#pragma unroll
    for (int b = 0; b < 4; b++){
        red[wid][b][lane]      = acc[b][0];
        red[wid][b][lane + 32] = acc[b][1];
    }
    __syncthreads();
    int o = threadIdx.x;
    int b = o >> 6, p = o & 63;
    float s = 0.f;
#pragma unroll
    for (int w = 0; w < 8; w++) s += red[w][b][p];
    PART[((mat*KSPLIT + ks)*4 + b)*64 + p] = s;
}

__global__ void vechead_final(const float* __restrict__ PART,
                              const float* __restrict__ b0, const float* __restrict__ b1,
                              const float* __restrict__ b2, const float* __restrict__ b3,
                              float* __restrict__ out){
    int o = blockIdx.x * 256 + threadIdx.x;
    if (o >= 4*4*64) return;
    int mat = o >> 8, rem = o & 255;
    int b = rem >> 6, p = rem & 63;
    float s = 0.f;
#pragma unroll
    for (int ks = 0; ks < KSPLIT; ks++) s += PART[((mat*KSPLIT + ks)*4 + b)*64 + p];
    const float* bias = (mat == 0) ? b0 : (mat == 1) ? b1 : (mat == 2) ? b2 : b3;
    int off = (mat == 0) ? 512 : (mat == 1) ? 768 : (mat == 2) ? 1536 : 1792;
    out[off + b*64 + p] = s + bias[p];
}

// ---------------- launcher ----------------
extern "C" void kernel_launch(void* const* d_in, const int* in_sizes, int n_in,
                              void* d_out, int out_size){
    const float* vis     = (const float*)d_in[0];
    const float* qry     = (const float*)d_in[1];
    const int*   vlen    = (const int*)  d_in[2];
    const float* vid_w1  = (const float*)d_in[3];
    const float* vid_b1  = (const float*)d_in[4];
    const float* vid_w2  = (const float*)d_in[5];
    const float* vid_b2  = (const float*)d_in[6];
    const float* s1_w1   = (const float*)d_in[7];
    const float* s1_b1   = (const float*)d_in[8];
    const float* s1_w2   = (const float*)d_in[9];
    const float* s1_b2   = (const float*)d_in[10];
    const float* s2_w1   = (const float*)d_in[11];
    const float* s2_b1   = (const float*)d_in[12];
    const float* s2_w2   = (const float*)d_in[13];
    const float* s2_b2   = (const float*)d_in[14];
    const float* proj_w  = (const float*)d_in[15];
    const float* proj_b  = (const float*)d_in[16];
    const float* st_w0   = (const float*)d_in[17];
    const float* st_b0   = (const float*)d_in[18];
    const float* en_w0   = (const float*)d_in[19];
    const float* en_b0   = (const float*)d_in[20];
    const float* sg_w0   = (const float*)d_in[21];
    const float* sg_b0   = (const float*)d_in[22];
    const float* st_w1   = (const float*)d_in[23];
    const float* st_b1   = (const float*)d_in[24];
    const float* en_w1   = (const float*)d_in[25];
    const float* en_b1   = (const float*)d_in[26];
    const float* sg_w1   = (const float*)d_in[27];
    const float* sg_b1   = (const float*)d_in[28];
    float* out = (float*)d_out;

    __half *Xvh, *Xvl, *Hh, *Hl, *Xqh, *Xql, *Hqh, *Hql, *Ah, *Al;
    __half *w1h, *w1l, *w2h, *w2l, *pwh, *pwl, *wq1h, *wq1l, *wq2h, *wq2l;
    float *V, *EP, *SIM, *CUM, *PARTS, *Md, *POOL, *PART, *BQ1, *BQ2;
    cudaGetSymbolAddress((void**)&Xvh, g_Xvh);
    cudaGetSymbolAddress((void**)&Xvl, g_Xvl);
    cudaGetSymbolAddress((void**)&Hh,  g_Hh);
    cudaGetSymbolAddress((void**)&Hl,  g_Hl);
    cudaGetSymbolAddress((void**)&V,   g_V);
    cudaGetSymbolAddress((void**)&Xqh, g_Xqh);
    cudaGetSymbolAddress((void**)&Xql, g_Xql);
    cudaGetSymbolAddress((void**)&Hqh, g_Hqh);
    cudaGetSymbolAddress((void**)&Hql, g_Hql);
    cudaGetSymbolAddress((void**)&EP,  g_ep);
    cudaGetSymbolAddress((void**)&SIM, g_sim);
    cudaGetSymbolAddress((void**)&CUM, g_cum);
    cudaGetSymbolAddress((void**)&PARTS, g_parts);
    cudaGetSymbolAddress((void**)&Ah,  g_Ah);
    cudaGetSymbolAddress((void**)&Al,  g_Al);
    cudaGetSymbolAddress((void**)&Md,  g_Md);
    cudaGetSymbolAddress((void**)&POOL,g_pool);
    cudaGetSymbolAddress((void**)&PART,g_part);
    cudaGetSymbolAddress((void**)&w1h, g_w1h);
    cudaGetSymbolAddress((void**)&w1l, g_w1l);
    cudaGetSymbolAddress((void**)&w2h, g_w2h);
    cudaGetSymbolAddress((void**)&w2l, g_w2l);
    cudaGetSymbolAddress((void**)&pwh, g_pwh);
    cudaGetSymbolAddress((void**)&pwl, g_pwl);
    cudaGetSymbolAddress((void**)&wq1h, g_wq1h);
    cudaGetSymbolAddress((void**)&wq1l, g_wq1l);
    cudaGetSymbolAddress((void**)&wq2h, g_wq2h);
    cudaGetSymbolAddress((void**)&wq2l, g_wq2l);
    cudaGetSymbolAddress((void**)&BQ1, g_bq1);
    cudaGetSymbolAddress((void**)&BQ2, g_bq2);

    cudaFuncSetAttribute(gemm_mma<1,0,1>, cudaFuncAttributeMaxDynamicSharedMemorySize, GM_SMEM);
    cudaFuncSetAttribute(gemm_mma<0,1,0>, cudaFuncAttributeMaxDynamicSharedMemorySize, GM_SMEM);

    // one-time aux stream + events (resources only; work identical each call)
    static cudaStream_t aux = nullptr;
    static cudaEvent_t evF, evT, evPE, evV, evS, evC, evL1;
    if (aux == nullptr){
        cudaStreamCreateWithFlags(&aux, cudaStreamNonBlocking);
        cudaEventCreateWithFlags(&evF,  cudaEventDisableTiming);
        cudaEventCreateWithFlags(&evT,  cudaEventDisableTiming);
        cudaEventCreateWithFlags(&evPE, cudaEventDisableTiming);
        cudaEventCreateWithFlags(&evV,  cudaEventDisableTiming);
        cudaEventCreateWithFlags(&evS,  cudaEventDisableTiming);
        cudaEventCreateWithFlags(&evC,  cudaEventDisableTiming);
        cudaEventCreateWithFlags(&evL1, cudaEventDisableTiming);
    }

    const int NSW_NONE = 1 << 30;

    // ---- fork at top ----
    cudaEventRecord(evF, 0);
    cudaStreamWaitEvent(aux, evF, 0);

    // aux: weight transposes + bias packs (overlaps PE-add on main)
    TSArgs ts;
    ts.src[0] = vid_w1; ts.dh[0] = w1h;  ts.dl[0] = w1l;
    ts.src[1] = vid_w2; ts.dh[1] = w2h;  ts.dl[1] = w2l;
    ts.src[2] = proj_w; ts.dh[2] = pwh;  ts.dl[2] = pwl;
    ts.src[3] = s1_w1;  ts.dh[3] = wq1h;           ts.dl[3] = wq1l;
    ts.src[4] = s2_w1;  ts.dh[4] = wq1h + 512*512; ts.dl[4] = wq1l + 512*512;
    ts.src[5] = s1_w2;  ts.dh[5] = wq2h;           ts.dl[5] = wq2l;
    ts.src[6] = s2_w2;  ts.dh[6] = wq2h + 512*512; ts.dl[6] = wq2l + 512*512;
    transpose_split_all<<<dim3(16,16,7), dim3(32,8), 0, aux>>>(ts);
    pack_biases<<<4, 512, 0, aux>>>(s1_b1, s2_b1, s1_b2, s2_b2, BQ1, BQ2);
    cudaEventRecord(evT, aux);

    // main: PE add + split (vis & query)
    add_pe_split_all<<<BB*TT + BB*WN, CC>>>(vis, Xvh, Xvl, qry, Xqh, Xql);
    cudaEventRecord(evPE, 0);
    cudaStreamWaitEvent(0, evT, 0);            // vid weights ready

    // aux: enc chain (Xq from PE; weights already on aux timeline)
    cudaStreamWaitEvent(aux, evPE, 0);
    gemm_mma<1,0,1><<<dim3(2*CC/64, BB*WN/64), 128, GM_SMEM, aux>>>(
        Xqh, Xql, wq1h, wq1l, BQ1, nullptr, Hqh, Hql, BB*WN, 2*CC, CC, CC, CC, NSW_NONE, 0);
    gemm_mma<0,1,0><<<dim3(2*CC/64, BB*WN/64), 128, GM_SMEM, aux>>>(
        Hqh, Hql, wq2h, wq2l, BQ2, EP, nullptr, nullptr, BB*WN, 2*CC, CC, 2*CC, CC, CC, CC);

    // main: vid MLP
    gemm_mma<1,0,1><<<dim3(CC/64, BB*TT/64), 128, GM_SMEM>>>(
        Xvh, Xvl, w1h, w1l, vid_b1, nullptr, Hh, Hl, BB*TT, CC, CC, CC, CC, NSW_NONE, 0);
    gemm_mma<0,1,0><<<dim3(CC/64, BB*TT/64), 128, GM_SMEM>>>(
        Hh, Hl, w2h, w2l, vid_b2, V, nullptr, nullptr, BB*TT, CC, CC, CC, CC, NSW_NONE, 0);
    cudaEventRecord(evV, 0);                   // V ready

    // aux: sim (needs V + EP), concurrent with cumsum on main
    cudaStreamWaitEvent(aux, evV, 0);
    sim_kernel<<<dim3(TT, BB), 256, 0, aux>>>(V, EP, SIM);
    cudaEventRecord(evS, aux);

    // main: chunked prefix sums of v
    cumsum_part_kernel<<<dim3(8, BB), 512>>>(V, PARTS);
    cumsum_write_kernel<<<dim3(8, BB), 512>>>(V, PARTS, CUM);
    cudaEventRecord(evC, 0);

    // aux: labelbuild window 1 (needs SIM + CUM); concurrent with w0 on main
    cudaStreamWaitEvent(aux, evC, 0);
    labelbuild_kernel<<<ROWS1, CC, 0, aux>>>(SIM, CUM, EP,
        Ah + (long)AOFF1*CC, Al + (long)AOFF1*CC, NT0_W1, 16);
    cudaEventRecord(evL1, aux);

    // main: labelbuild window 0, then join and run ONE merged projection GEMM
    cudaStreamWaitEvent(0, evS, 0);
    labelbuild_kernel<<<ROWS0, CC>>>(SIM, CUM, EP, Ah, Al, NT0_W0, 8);
    cudaStreamWaitEvent(0, evL1, 0);
    gemm_mma<0,1,0><<<dim3(DD/64, 4096/64), 128, GM_SMEM>>>(
        Ah, Al, pwh, pwl, proj_b, Md, nullptr, nullptr, 4096, DD, CC, CC, CC, NSW_NONE, 0);

    // pool both windows, then heads (merged kernels, main stream)
    pool_kernel<<<dim3(PP, BB, 2), DD>>>(vlen, Md, POOL);

    SegArgs sa;
    sa.sw[0] = sg_w0; sa.sb[0] = sg_b0;
    sa.sw[1] = sg_w1; sa.sb[1] = sg_b1;
    seg_kernel<<<dim3(PP, BB, 2), 128>>>(sa, POOL, out);

    VHArgs vh;
    vh.W[0] = st_w0; vh.W[1] = en_w0; vh.W[2] = st_w1; vh.W[3] = en_w1;
    vechead_partial<<<dim3(KSPLIT, 4), 256>>>(vh, POOL, PART);
    vechead_final<<<4, 256>>>(PART, st_b0, en_b0, st_b1, en_b1, out);
}

// round 14
// speedup vs baseline: 1.2083x; 1.0310x over previous
#include <cuda_runtime.h>
#include <cuda_fp16.h>
#include <math.h>
#include <stdint.h>

// Problem constants (fixed shapes)
#define BB 4
#define TT 512
#define CC 512
#define WN 32
#define DD 512
#define PP 64

#define NT0_W0 (TT-8+1)          // 505
#define NT0_W1 (TT-16+1)         // 497
#define ROWS0 (BB*NT0_W0)        // 2020
#define ROWS1 (BB*NT0_W1)        // 1988
#define AOFF1 2048               // window-1 A/Md row offset (pad rows stay zero)

// ---------------- scratch (static device globals; no allocation) ----------------
__device__ __half g_Xvh[BB*TT*CC], g_Xvl[BB*TT*CC];
__device__ __half g_Hh [BB*TT*CC], g_Hl [BB*TT*CC];
__device__ float g_V  [BB*TT*CC];
__device__ __half g_Xqh[BB*WN*CC], g_Xql[BB*WN*CC];
__device__ __half g_Hqh[BB*WN*2*CC], g_Hql[BB*WN*2*CC];   // [128, 1024]
__device__ float g_ep [BB*WN*2*CC];                        // [128, 1024] = [E1 | E2]
__device__ float g_sim[BB*TT*WN];
__device__ float g_cum[BB*(TT+1)*CC];
__device__ float g_parts[BB*8*CC];
__device__ __half g_Ah[4096*CC], g_Al[4096*CC];   // zero-init; pad rows never written
__device__ float g_Md [4096*DD];
__device__ float g_pool[2*BB*PP*DD];               // per-window buffers
__device__ float g_part[4*64*BB*PP];
__device__ float g_dummy[256];                     // prefetch sink (never read)
__device__ __half g_w1h[CC*CC],   g_w1l[CC*CC];    // vid_w1^T
__device__ __half g_w2h[CC*CC],   g_w2l[CC*CC];    // vid_w2^T
__device__ __half g_pwh[CC*DD],   g_pwl[CC*DD];    // proj_w^T
__device__ __half g_wq1h[2*CC*CC],g_wq1l[2*CC*CC]; // [s1_w1^T ; s2_w1^T]
__device__ __half g_wq2h[2*CC*CC],g_wq2l[2*CC*CC]; // [s1_w2^T ; s2_w2^T]
__device__ float g_bq1[2*CC];                       // [s1_b1 ; s2_b1]
__device__ float g_bq2[2*CC];                       // [s1_b2 ; s2_b2]

static inline int cdiv(int a, int b){ return (a + b - 1) / b; }

// ---------------- mma.sync helpers (sm_80+ path; legal on plain sm_100) ----------------
__device__ __forceinline__ uint32_t smem_to_u32(const void* p) {
    uint32_t a;
    asm("{ .reg .u64 tmp; cvta.to.shared.u64 tmp, %1; cvt.u32.u64 %0, tmp; }" : "=r"(a) : "l"(p));
    return a;
}
__device__ __forceinline__ void ldmx4(uint32_t* r, uint32_t addr){
    asm volatile("ldmatrix.sync.aligned.m8n8.x4.shared.b16 {%0,%1,%2,%3}, [%4];"
        : "=r"(r[0]),"=r"(r[1]),"=r"(r[2]),"=r"(r[3]) : "r"(addr));
}
__device__ __forceinline__ void mma16816(float* c, const uint32_t* a, uint32_t b0, uint32_t b1){
    asm volatile("mma.sync.aligned.m16n8k16.row.col.f32.f16.f16.f32 "
        "{%0,%1,%2,%3}, {%4,%5,%6,%7}, {%8,%9}, {%0,%1,%2,%3};"
        : "+f"(c[0]),"+f"(c[1]),"+f"(c[2]),"+f"(c[3])
        : "r"(a[0]),"r"(a[1]),"r"(a[2]),"r"(a[3]), "r"(b0),"r"(b1));
}
__device__ __forceinline__ void cp_async16(uint32_t saddr, const void* gaddr){
    asm volatile("cp.async.cg.shared.global [%0], [%1], 16;" :: "r"(saddr), "l"(gaddr));
}
// fp16 hi/lo split: hi+lo captures ~22 mantissa bits of v
__device__ __forceinline__ void split_h(float v, __half& h, __half& l){
    h = __float2half_rn(v);
    l = __float2half_rn(v - __half2float(h));
}

// ---------- tensor-core fp16-split GEMM: C = (Ah+Al)@(Bh+Bl)^T, 3 products ----------
// Block tile 64x64, 4 warps (2m x 2n), warp tile 32x32, K-chunk 32.
// 3-stage smem pipeline + fragment double-buffer. 4 CTAs/SM (128 threads).
// If n0 >= nswitch, A pointers shift by aoff elements (fuses two GEMMs along N).
#define GM_STG 16384
#define GM_SMEM (3*16384)

template<int RELU, int WF, int WS>
__global__ void __launch_bounds__(128, 4)
gemm_mma(const __half* __restrict__ Ah, const __half* __restrict__ Al,
         const __half* __restrict__ Bh, const __half* __restrict__ Bl,
         const float* __restrict__ bias, float* __restrict__ outF,
         __half* __restrict__ outH, __half* __restrict__ outL,
         int M, int N, int K, int lda, int ldb, int nswitch, int aoff)
{
    extern __shared__ char smem[];
    uint32_t sbase = smem_to_u32(smem);
    int tid = threadIdx.x;
    int warp = tid >> 5, lane = tid & 31;
    int wm = warp & 1, wn = warp >> 1;          // 2m x 2n warps
    int m0 = blockIdx.y << 6, n0 = blockIdx.x << 6;
    if (n0 >= nswitch){ Ah += aoff; Al += aoff; }

    float acc[2][4][4];
#pragma unroll
    for (int a = 0; a < 2; a++)
#pragma unroll
        for (int b = 0; b < 4; b++)
#pragma unroll
            for (int c = 0; c < 4; c++) acc[a][b][c] = 0.f;

    int nch = K >> 5;

    auto load_chunk = [&](int ch){
        int stage = ch % 3;
        int k0 = ch << 5;
#pragma unroll
        for (int j = 0; j < 8; j++){
            int i = tid + (j << 7);             // 0..1023
            int tile = i >> 8;                  // 0:Ah 1:Al 2:Bh 3:Bl
            int rem = i & 255;
            int g = rem >> 6, r = rem & 63;
            const __half* gp;
            if (tile < 2) gp = (tile ? Al : Ah) + (long)(m0 + r)*lda + k0 + (g << 3);
            else          gp = ((tile & 1) ? Bl : Bh) + (long)(n0 + r)*ldb + k0 + (g << 3);
            uint32_t sa = sbase + stage*GM_STG + (tile << 12) + (g << 10) + (r << 4);
            cp_async16(sa, gp);
        }
        asm volatile("cp.async.commit_group;");
    };

    load_chunk(0);
    if (nch > 1) load_chunk(1);

    int ra = lane & 15;
    int ghalf = lane >> 4;

    for (int ch = 0; ch < nch; ch++){
        if (ch + 1 < nch) asm volatile("cp.async.wait_group 1;");
        else              asm volatile("cp.async.wait_group 0;");
        __syncthreads();
        if (ch + 2 < nch) load_chunk(ch + 2);

        uint32_t st = sbase + (ch % 3)*GM_STG;

        uint32_t a_h[2][2][4], a_l[2][2][4], b_h[2][2][4], b_l[2][2][4];

        auto load_frag = [&](int ks, int buf){
            int ga = (ks << 1) + ghalf;
#pragma unroll
            for (int mt = 0; mt < 2; mt++){
                int r = (wm << 5) + (mt << 4) + ra;
                uint32_t off = (uint32_t)((ga << 10) + (r << 4));
                ldmx4(a_h[buf][mt], st + off);
                ldmx4(a_l[buf][mt], st + 4096 + off);
            }
#pragma unroll
            for (int np = 0; np < 2; np++){
                int r = (wn << 5) + (np << 4) + ra;
                uint32_t off = (uint32_t)((ga << 10) + (r << 4));
                ldmx4(b_h[buf][np], st + 8192  + off);
                ldmx4(b_l[buf][np], st + 12288 + off);
            }
        };

        load_frag(0, 0);
#pragma unroll
        for (int ks = 0; ks < 2; ks++){
            int buf = ks & 1;
            if (ks == 0) load_frag(1, 1);
#pragma unroll
            for (int mt = 0; mt < 2; mt++)
#pragma unroll
                for (int nt = 0; nt < 4; nt++){
                    int np = nt >> 1, pr = nt & 1;
                    mma16816(acc[mt][nt], a_h[buf][mt], b_h[buf][np][pr], b_h[buf][np][pr+2]);
                    mma16816(acc[mt][nt], a_h[buf][mt], b_l[buf][np][pr], b_l[buf][np][pr+2]);
                    mma16816(acc[mt][nt], a_l[buf][mt], b_h[buf][np][pr], b_h[buf][np][pr+2]);
                }
        }
    }
    __syncthreads();

    // epilogue
    int col_base = n0 + (wn << 5);
    int r0 = lane >> 2;
    int cp2 = (lane & 3) << 1;
#pragma unroll
    for (int mt = 0; mt < 2; mt++){
        int row_base = m0 + (wm << 5) + (mt << 4);
#pragma unroll
        for (int i = 0; i < 2; i++){
            int m = row_base + r0 + (i << 3);
#pragma unroll
            for (int nt = 0; nt < 4; nt++){
                int col = col_base + (nt << 3) + cp2;
                float v0 = acc[mt][nt][i*2+0] + bias[col];
                float v1 = acc[mt][nt][i*2+1] + bias[col+1];
                if (RELU){ v0 = fmaxf(v0, 0.f); v1 = fmaxf(v1, 0.f); }
                if (WF){
                    float2 o; o.x = v0; o.y = v1;
                    *(float2*)&outF[(long)m*N + col] = o;
                }
                if (WS){
                    __half h0, l0, h1, l1;
                    split_h(v0, h0, l0);
                    split_h(v1, h1, l1);
                    *(__half2*)&outH[(long)m*N + col] = __halves2half2(h0, h1);
                    *(__half2*)&outL[(long)m*N + col] = __halves2half2(l0, l1);
                }
            }
        }
    }
}

// ---------------- small kernels ----------------

// PE add + fp16 split for vis (rows < 2048) and query (rows >= 2048)
__global__ void add_pe_split_all(const float* __restrict__ xv,
                                 __half* __restrict__ xvh, __half* __restrict__ xvl,
                                 const float* __restrict__ xq,
                                 __half* __restrict__ xqh, __half* __restrict__ xql){
    int row = blockIdx.x;
    int c = threadIdx.x;
    const float* x; __half *yh, *yl; int t;
    if (row < BB*TT){ x = xv; yh = xvh; yl = xvl; t = row % TT; }
    else { row -= BB*TT; x = xq; yh = xqh; yl = xql; t = row % WN; }
    int i2 = (c >> 1) << 1;
    float ang = (float)t * expf((float)i2 * -1.7988946039352293e-2f);
    float pe = (c & 1) ? cosf(ang) : sinf(ang);
    float v = x[row*CC + c] + pe;
    __half h, l; split_h(v, h, l);
    yh[row*CC + c] = h; yl[row*CC + c] = l;
}

// batched 512x512 transpose+split (z=0..6) + bias packing (z=7)
struct TSArgs {
    const float* src[7]; __half* dh[7]; __half* dl[7];
    const float* bsrc[4]; float* bdst1; float* bdst2;
};
__global__ void transpose_split_all(TSArgs a){
    int z = blockIdx.z;
    if (z == 7){
        int idx = (blockIdx.y*16 + blockIdx.x)*256 + threadIdx.y*32 + threadIdx.x;
        if (idx < 2048){
            int seg = idx >> 9, i = idx & 511;
            float v = a.bsrc[seg][i];
            if (seg == 0) a.bdst1[i] = v;
            else if (seg == 1) a.bdst1[512 + i] = v;
            else if (seg == 2) a.bdst2[i] = v;
            else a.bdst2[512 + i] = v;
        }
        return;
    }
    const float* W = a.src[z];
    __half* Th = a.dh[z];
    __half* Tl = a.dl[z];
    __shared__ float t[32][33];
    int bx = blockIdx.x << 5, by = blockIdx.y << 5;
    int x = threadIdx.x, y = threadIdx.y;
#pragma unroll
    for (int i = 0; i < 32; i += 8) t[y+i][x] = W[(long)(by + y + i)*512 + bx + x];
    __syncthreads();
#pragma unroll
    for (int i = 0; i < 32; i += 8){
        float v = t[x][y+i];
        __half h, l; split_h(v, h, l);
        long o = (long)(bx + y + i)*512 + by + x;
        Th[o] = h; Tl[o] = l;
    }
}

// sim[b, t, w] = dot(v[b,t,:], E1[b,w,:]); E1 = EP[:, 0:512] with row stride 1024
__global__ void sim_kernel(const float* __restrict__ V, const float* __restrict__ EP,
                           float* __restrict__ SIM){
    int t = blockIdx.x, b = blockIdx.y;
    __shared__ float vrow[CC];
    int tid = threadIdx.x;
    const float* vp = &V[(b*TT + t)*CC];
    vrow[tid]       = vp[tid];
    vrow[tid + 256] = vp[tid + 256];
    __syncthreads();
    int wid = tid >> 5, lane = tid & 31;
    for (int w = wid; w < WN; w += 8){
        const float* e = &EP[(b*WN + w)*(2*CC)];
        float sum = 0.f;
        for (int c = lane; c < CC; c += 32) sum = fmaf(vrow[c], e[c], sum);
#pragma unroll
        for (int off = 16; off; off >>= 1) sum += __shfl_down_sync(0xffffffffu, sum, off);
        if (lane == 0) SIM[(b*TT + t)*WN + w] = sum;
    }
}

// two-pass chunked exclusive cumsum over t
__global__ void cumsum_part_kernel(const float* __restrict__ V, float* __restrict__ PARTS){
    int c = threadIdx.x;
    int chunk = blockIdx.x;
    int b = blockIdx.y;
    float s = 0.f;
    const float* p = &V[((b*TT) + (chunk << 6))*CC + c];
#pragma unroll 8
    for (int u = 0; u < 64; u++) s += p[u*CC];
    PARTS[(b*8 + chunk)*CC + c] = s;
}

__global__ void cumsum_write_kernel(const float* __restrict__ V, const float* __restrict__ PARTS,
                                    float* __restrict__ CUM){
    int c = threadIdx.x;
    int chunk = blockIdx.x;
    int b = blockIdx.y;
    float base = 0.f;
    for (int j = 0; j < chunk; j++) base += PARTS[(b*8 + j)*CC + c];
    int t0 = chunk << 6;
    const float* vp = &V[((b*TT) + t0)*CC + c];
    float* cp = &CUM[((b*(TT+1)) + t0)*CC + c];
    float acc = base;
#pragma unroll 8
    for (int u = 0; u < 64; u++){
        cp[u*CC] = acc;
        acc += vp[u*CC];
    }
    if (chunk == 7) cp[64*CC] = acc;
}

// fused labels (warp-0 argmax) + split-A row build; ONE window per launch
__global__ void labelbuild_kernel(const float* __restrict__ SIM, const float* __restrict__ CUM,
                                  const float* __restrict__ EP,
                                  __half* __restrict__ Aho, __half* __restrict__ Alo,
                                  int nt0, int s){
    int row = blockIdx.x;                      // 0..BB*nt0-1
    int b = row / nt0, t0 = row % nt0;
    __shared__ int slab;
    int tid = threadIdx.x;                     // 512
    if (tid < 32){
        const float* sp = &SIM[(b*TT + t0)*WN + tid];
        float sum = 0.f;
        for (int u = 0; u < s; u++) sum += sp[u*WN];
        float best = sum; int bi = tid;
#pragma unroll
        for (int off = 16; off; off >>= 1){
            float ov = __shfl_down_sync(0xffffffffu, best, off);
            int   oi = __shfl_down_sync(0xffffffffu, bi,   off);
            if (ov > best || (ov == best && oi < bi)){ best = ov; bi = oi; }
        }
        if (tid == 0) slab = bi;
    }
    __syncthreads();
    int lab = slab;
    int c = tid;
    float vu = (CUM[(b*(TT+1) + t0 + s)*CC + c] - CUM[(b*(TT+1) + t0)*CC + c]) * (1.f/(float)s);
    float v = vu * EP[(b*WN + lab)*(2*CC) + CC + c];
    __half h, l; split_h(v, h, l);
    Aho[(long)row*CC + c] = h;
    Alo[(long)row*CC + c] = l;
}

// fused adaptive max pool + seg head; z = window (Md rows at 0 / AOFF1)
struct SegArgs { const float* sw[2]; const float* sb[2]; };
__global__ void pool_seg_kernel(const int* __restrict__ vid_len, const float* __restrict__ Md,
                                float* __restrict__ POOL, SegArgs a, float* __restrict__ out){
    int i = blockIdx.x, b = blockIdx.y, z = blockIdx.z;
    int d = threadIdx.x;                       // 512
    int s   = z ? 16 : 8;
    int nt0 = TT - s + 1;
    const float* Mw = Md + (long)(z ? AOFF1 : 0)*DD;
    float* PO = POOL + (long)z*BB*PP*DD;
    int Lin = vid_len[b] * 8;
    if (Lin < 1) Lin = 1;
    int start = (i * Lin) >> 6;
    int end   = ((i + 1) * Lin + 63) >> 6;
    const float* base = Mw + (long)b*nt0*DD + d;
    float m = -3.402823466e38f;
    for (int r = start; r < end; r++){
        int t0 = (r >> 3) + (r & 7) * s;
        float v = base[(long)t0*DD];
        m = fmaxf(m, v);
    }
    PO[(b*PP + i)*DD + d] = m;

    // seg head: dot over d of pooled row with sw[:,0] / sw[:,1]
    const float* sw = a.sw[z];
    float a0 = m * sw[2*d];
    float a1 = m * sw[2*d + 1];
    int lane = d & 31, wid = d >> 5;
#pragma unroll
    for (int off = 16; off; off >>= 1){
        a0 += __shfl_down_sync(0xffffffffu, a0, off);
        a1 += __shfl_down_sync(0xffffffffu, a1, off);
    }
    __shared__ float s0[16], s1[16];
    if (lane == 0){ s0[wid] = a0; s1[wid] = a1; }
    __syncthreads();
    if (d == 0){
        const float* sb = a.sb[z];
        float r0 = 0.f, r1 = 0.f;
#pragma unroll
        for (int w = 0; w < 16; w++){ r0 += s0[w]; r1 += s1[w]; }
        int obase = z ? 1024 : 0;
        out[obase + b*128 + i]      = r0 + sb[0];
        out[obase + b*128 + 64 + i] = r1 + sb[1];
    }
}

// st/en heads: 4 matrices x 64 k-splits in one launch
#define KSPLIT 64
struct VHArgs { const float* W[4]; };
__global__ void vechead_partial(VHArgs a, const float* __restrict__ POOL,
                                float* __restrict__ PART){
    int ks = blockIdx.x;
    int mat = blockIdx.y;                      // 0=st0 1=en0 2=st1 3=en1
    const float* W = a.W[mat];
    const float* PO = POOL + (long)(mat >> 1)*BB*PP*DD;
    int wid = threadIdx.x >> 5, lane = threadIdx.x & 31;
    float acc[4][2] = {{0.f,0.f},{0.f,0.f},{0.f,0.f},{0.f,0.f}};
    int kbase = ks * 512;
    for (int kk = wid; kk < 512; kk += 8){
        int k = kbase + kk;
        float w0 = W[k*64 + lane];
        float w1 = W[k*64 + 32 + lane];
        int p = k & 63, d = k >> 6;
#pragma unroll
        for (int b = 0; b < 4; b++){
            float v = PO[(b*PP + p)*DD + d];
            acc[b][0] = fmaf(v, w0, acc[b][0]);
            acc[b][1] = fmaf(v, w1, acc[b][1]);
        }
    }
    __shared__ float red[8][4][64];
#pragma unroll
    for (int b = 0; b < 4; b++){
        red[wid][b][lane]      = acc[b][0];
        red[wid][b][lane + 32] = acc[b][1];
    }
    __syncthreads();
    int o = threadIdx.x;
    int b = o >> 6, p = o & 63;
    float s = 0.f;
#pragma unroll
    for (int w = 0; w < 8; w++) s += red[w][b][p];
    PART[((mat*KSPLIT + ks)*4 + b)*64 + p] = s;
}

__global__ void vechead_final(const float* __restrict__ PART,
                              const float* __restrict__ b0, const float* __restrict__ b1,
                              const float* __restrict__ b2, const float* __restrict__ b3,
                              float* __restrict__ out){
    int o = blockIdx.x * 256 + threadIdx.x;
    if (o >= 4*4*64) return;
    int mat = o >> 8, rem = o & 255;
    int b = rem >> 6, p = rem & 63;
    float s = 0.f;
#pragma unroll
    for (int ks = 0; ks < KSPLIT; ks++) s += PART[((mat*KSPLIT + ks)*4 + b)*64 + p];
    const float* bias = (mat == 0) ? b0 : (mat == 1) ? b1 : (mat == 2) ? b2 : b3;
    int off = (mat == 0) ? 512 : (mat == 1) ? 768 : (mat == 2) ? 1536 : 1792;
    out[off + b*64 + p] = s + bias[p];
}

// L2 warm-up for st/en weights (32MB); sums into write-only scratch
struct PFArgs { const float* W[4]; };
__global__ void prefetch_kernel(PFArgs a, float* __restrict__ sink){
    float s = 0.f;
    int tid = threadIdx.x;
    const int n4 = 32768*64/4;                 // float4 per matrix
#pragma unroll
    for (int m = 0; m < 4; m++){
        const float4* p = (const float4*)a.W[m];
        for (int i = blockIdx.x*256 + tid; i < n4; i += 256*256){
            float4 v = p[i];
            s += v.x + v.y + v.z + v.w;
        }
    }
    __shared__ float red[256];
    red[tid] = s;
    __syncthreads();
    if (tid == 0){
        float t = 0.f;
        for (int i = 0; i < 256; i++) t += red[i];
        sink[blockIdx.x] = t;
    }
}

// ---------------- launcher ----------------
extern "C" void kernel_launch(void* const* d_in, const int* in_sizes, int n_in,
                              void* d_out, int out_size){
    const float* vis     = (const float*)d_in[0];
    const float* qry     = (const float*)d_in[1];
    const int*   vlen    = (const int*)  d_in[2];
    const float* vid_w1  = (const float*)d_in[3];
    const float* vid_b1  = (const float*)d_in[4];
    const float* vid_w2  = (const float*)d_in[5];
    const float* vid_b2  = (const float*)d_in[6];
    const float* s1_w1   = (const float*)d_in[7];
    const float* s1_b1   = (const float*)d_in[8];
    const float* s1_w2   = (const float*)d_in[9];
    const float* s1_b2   = (const float*)d_in[10];
    const float* s2_w1   = (const float*)d_in[11];
    const float* s2_b1   = (const float*)d_in[12];
    const float* s2_w2   = (const float*)d_in[13];
    const float* s2_b2   = (const float*)d_in[14];
    const float* proj_w  = (const float*)d_in[15];
    const float* proj_b  = (const float*)d_in[16];
    const float* st_w0   = (const float*)d_in[17];
    const float* st_b0   = (const float*)d_in[18];
    const float* en_w0   = (const float*)d_in[19];
    const float* en_b0   = (const float*)d_in[20];
    const float* sg_w0   = (const float*)d_in[21];
    const float* sg_b0   = (const float*)d_in[22];
    const float* st_w1   = (const float*)d_in[23];
    const float* st_b1   = (const float*)d_in[24];
    const float* en_w1   = (const float*)d_in[25];
    const float* en_b1   = (const float*)d_in[26];
    const float* sg_w1   = (const float*)d_in[27];
    const float* sg_b1   = (const float*)d_in[28];
    float* out = (float*)d_out;

    __half *Xvh, *Xvl, *Hh, *Hl, *Xqh, *Xql, *Hqh, *Hql, *Ah, *Al;
    __half *w1h, *w1l, *w2h, *w2l, *pwh, *pwl, *wq1h, *wq1l, *wq2h, *wq2l;
    float *V, *EP, *SIM, *CUM, *PARTS, *Md, *POOL, *PART, *BQ1, *BQ2, *SINK;
    cudaGetSymbolAddress((void**)&Xvh, g_Xvh);
    cudaGetSymbolAddress((void**)&Xvl, g_Xvl);
    cudaGetSymbolAddress((void**)&Hh,  g_Hh);
    cudaGetSymbolAddress((void**)&Hl,  g_Hl);
    cudaGetSymbolAddress((void**)&V,   g_V);
    cudaGetSymbolAddress((void**)&Xqh, g_Xqh);
    cudaGetSymbolAddress((void**)&Xql, g_Xql);
    cudaGetSymbolAddress((void**)&Hqh, g_Hqh);
    cudaGetSymbolAddress((void**)&Hql, g_Hql);
    cudaGetSymbolAddress((void**)&EP,  g_ep);
    cudaGetSymbolAddress((void**)&SIM, g_sim);
    cudaGetSymbolAddress((void**)&CUM, g_cum);
    cudaGetSymbolAddress((void**)&PARTS, g_parts);
    cudaGetSymbolAddress((void**)&Ah,  g_Ah);
    cudaGetSymbolAddress((void**)&Al,  g_Al);
    cudaGetSymbolAddress((void**)&Md,  g_Md);
    cudaGetSymbolAddress((void**)&POOL,g_pool);
    cudaGetSymbolAddress((void**)&PART,g_part);
    cudaGetSymbolAddress((void**)&SINK,g_dummy);
    cudaGetSymbolAddress((void**)&w1h, g_w1h);
    cudaGetSymbolAddress((void**)&w1l, g_w1l);
    cudaGetSymbolAddress((void**)&w2h, g_w2h);
    cudaGetSymbolAddress((void**)&w2l, g_w2l);
    cudaGetSymbolAddress((void**)&pwh, g_pwh);
    cudaGetSymbolAddress((void**)&pwl, g_pwl);
    cudaGetSymbolAddress((void**)&wq1h, g_wq1h);
    cudaGetSymbolAddress((void**)&wq1l, g_wq1l);
    cudaGetSymbolAddress((void**)&wq2h, g_wq2h);
    cudaGetSymbolAddress((void**)&wq2l, g_wq2l);
    cudaGetSymbolAddress((void**)&BQ1, g_bq1);
    cudaGetSymbolAddress((void**)&BQ2, g_bq2);

    cudaFuncSetAttribute(gemm_mma<1,0,1>, cudaFuncAttributeMaxDynamicSharedMemorySize, GM_SMEM);
    cudaFuncSetAttribute(gemm_mma<0,1,0>, cudaFuncAttributeMaxDynamicSharedMemorySize, GM_SMEM);

    // one-time aux stream + events (resources only; work identical each call)
    static cudaStream_t aux = nullptr;
    static cudaEvent_t evF, evT, evPE, evV, evS, evC, evL1, evPF;
    if (aux == nullptr){
        cudaStreamCreateWithFlags(&aux, cudaStreamNonBlocking);
        cudaEventCreateWithFlags(&evF,  cudaEventDisableTiming);
        cudaEventCreateWithFlags(&evT,  cudaEventDisableTiming);
        cudaEventCreateWithFlags(&evPE, cudaEventDisableTiming);
        cudaEventCreateWithFlags(&evV,  cudaEventDisableTiming);
        cudaEventCreateWithFlags(&evS,  cudaEventDisableTiming);
        cudaEventCreateWithFlags(&evC,  cudaEventDisableTiming);
        cudaEventCreateWithFlags(&evL1, cudaEventDisableTiming);
        cudaEventCreateWithFlags(&evPF, cudaEventDisableTiming);
    }

    const int NSW_NONE = 1 << 30;

    // ---- fork at top ----
    cudaEventRecord(evF, 0);
    cudaStreamWaitEvent(aux, evF, 0);

    // aux: weight transposes + bias packs (z=7) — overlaps PE-add on main
    TSArgs ts;
    ts.src[0] = vid_w1; ts.dh[0] = w1h;  ts.dl[0] = w1l;
    ts.src[1] = vid_w2; ts.dh[1] = w2h;  ts.dl[1] = w2l;
    ts.src[2] = proj_w; ts.dh[2] = pwh;  ts.dl[2] = pwl;
    ts.src[3] = s1_w1;  ts.dh[3] = wq1h;           ts.dl[3] = wq1l;
    ts.src[4] = s2_w1;  ts.dh[4] = wq1h + 512*512; ts.dl[4] = wq1l + 512*512;
    ts.src[5] = s1_w2;  ts.dh[5] = wq2h;           ts.dl[5] = wq2l;
    ts.src[6] = s2_w2;  ts.dh[6] = wq2h + 512*512; ts.dl[6] = wq2l + 512*512;
    ts.bsrc[0] = s1_b1; ts.bsrc[1] = s2_b1; ts.bsrc[2] = s1_b2; ts.bsrc[3] = s2_b2;
    ts.bdst1 = BQ1; ts.bdst2 = BQ2;
    transpose_split_all<<<dim3(16,16,8), dim3(32,8), 0, aux>>>(ts);
    cudaEventRecord(evT, aux);

    // main: PE add + split (vis & query)
    add_pe_split_all<<<BB*TT + BB*WN, CC>>>(vis, Xvh, Xvl, qry, Xqh, Xql);
    cudaEventRecord(evPE, 0);
    cudaStreamWaitEvent(0, evT, 0);            // vid weights ready

    // aux: enc chain (Xq from PE; weights already on aux timeline)
    cudaStreamWaitEvent(aux, evPE, 0);
    gemm_mma<1,0,1><<<dim3(2*CC/64, BB*WN/64), 128, GM_SMEM, aux>>>(
        Xqh, Xql, wq1h, wq1l, BQ1, nullptr, Hqh, Hql, BB*WN, 2*CC, CC, CC, CC, NSW_NONE, 0);
    gemm_mma<0,1,0><<<dim3(2*CC/64, BB*WN/64), 128, GM_SMEM, aux>>>(
        Hqh, Hql, wq2h, wq2l, BQ2, EP, nullptr, nullptr, BB*WN, 2*CC, CC, 2*CC, CC, CC, CC);

    // main: vid MLP
    gemm_mma<1,0,1><<<dim3(CC/64, BB*TT/64), 128, GM_SMEM>>>(
        Xvh, Xvl, w1h, w1l, vid_b1, nullptr, Hh, Hl, BB*TT, CC, CC, CC, CC, NSW_NONE, 0);
    gemm_mma<0,1,0><<<dim3(CC/64, BB*TT/64), 128, GM_SMEM>>>(
        Hh, Hl, w2h, w2l, vid_b2, V, nullptr, nullptr, BB*TT, CC, CC, CC, CC, NSW_NONE, 0);
    cudaEventRecord(evV, 0);                   // V ready

    // aux: sim (needs V + EP), concurrent with cumsum on main
    cudaStreamWaitEvent(aux, evV, 0);
    sim_kernel<<<dim3(TT, BB), 256, 0, aux>>>(V, EP, SIM);
    cudaEventRecord(evS, aux);

    // main: chunked prefix sums of v
    cumsum_part_kernel<<<dim3(8, BB), 512>>>(V, PARTS);
    cumsum_write_kernel<<<dim3(8, BB), 512>>>(V, PARTS, CUM);
    cudaEventRecord(evC, 0);

    // aux: labelbuild window 1, then L2 prefetch of head weights (under proj)
    cudaStreamWaitEvent(aux, evC, 0);
    labelbuild_kernel<<<ROWS1, CC, 0, aux>>>(SIM, CUM, EP,
        Ah + (long)AOFF1*CC, Al + (long)AOFF1*CC, NT0_W1, 16);
    cudaEventRecord(evL1, aux);
    PFArgs pf;
    pf.W[0] = st_w0; pf.W[1] = en_w0; pf.W[2] = st_w1; pf.W[3] = en_w1;
    prefetch_kernel<<<256, 256, 0, aux>>>(pf, SINK);
    cudaEventRecord(evPF, aux);

    // main: labelbuild window 0, join lb_w1, ONE merged projection GEMM
    cudaStreamWaitEvent(0, evS, 0);
    labelbuild_kernel<<<ROWS0, CC>>>(SIM, CUM, EP, Ah, Al, NT0_W0, 8);
    cudaStreamWaitEvent(0, evL1, 0);
    gemm_mma<0,1,0><<<dim3(DD/64, 4096/64), 128, GM_SMEM>>>(
        Ah, Al, pwh, pwl, proj_b, Md, nullptr, nullptr, 4096, DD, CC, CC, CC, NSW_NONE, 0);

    // fused pool + seg (both windows), then vechead
    SegArgs sa;
    sa.sw[0] = sg_w0; sa.sb[0] = sg_b0;
    sa.sw[1] = sg_w1; sa.sb[1] = sg_b1;
    pool_seg_kernel<<<dim3(PP, BB, 2), DD>>>(vlen, Md, POOL, sa, out);

    VHArgs vh;
    vh.W[0] = st_w0; vh.W[1] = en_w0; vh.W[2] = st_w1; vh.W[3] = en_w1;
    vechead_partial<<<dim3(KSPLIT, 4), 256>>>(vh, POOL, PART);
    cudaStreamWaitEvent(0, evPF, 0);           // join prefetch (long since done)
    vechead_final<<<4, 256>>>(PART, st_b0, en_b0, st_b1, en_b1, out);
}

// round 15
// speedup vs baseline: 1.2255x; 1.0142x over previous
#include <cuda_runtime.h>
#include <cuda_fp16.h>
#include <math.h>
#include <stdint.h>

// Problem constants (fixed shapes)
#define BB 4
#define TT 512
#define CC 512
#define WN 32
#define DD 512
#define PP 64

#define NT0_W0 (TT-8+1)          // 505
#define NT0_W1 (TT-16+1)         // 497
#define ROWS0 (BB*NT0_W0)        // 2020
#define ROWS1 (BB*NT0_W1)        // 1988
#define AOFF1 2048               // window-1 A/Md row offset (pad rows stay zero)

// ---------------- scratch (static device globals; no allocation) ----------------
__device__ __half g_Xvh[BB*TT*CC], g_Xvl[BB*TT*CC];
__device__ __half g_Hh [BB*TT*CC], g_Hl [BB*TT*CC];
__device__ float g_V  [BB*TT*CC];
__device__ __half g_Xqh[BB*WN*CC], g_Xql[BB*WN*CC];
__device__ __half g_Hqh[BB*WN*2*CC], g_Hql[BB*WN*2*CC];   // [128, 1024]
__device__ float g_ep [BB*WN*2*CC];                        // [128, 1024] = [E1 | E2]
__device__ float g_sim[BB*TT*WN];
__device__ float g_cum[BB*(TT+1)*CC];
__device__ float g_parts[BB*8*CC];
__device__ __half g_Ah[4096*CC], g_Al[4096*CC];   // zero-init; pad rows never written
__device__ float g_Md [4096*DD];
__device__ float g_pool[2*BB*PP*DD];               // per-window buffers
__device__ float g_part[4*64*BB*PP];
__device__ float g_dummy[256];                     // prefetch sink (never read)
__device__ __half g_w1h[CC*CC],   g_w1l[CC*CC];    // vid_w1^T
__device__ __half g_w2h[CC*CC],   g_w2l[CC*CC];    // vid_w2^T
__device__ __half g_pwh[CC*DD],   g_pwl[CC*DD];    // proj_w^T
__device__ __half g_wq1h[2*CC*CC],g_wq1l[2*CC*CC]; // [s1_w1^T ; s2_w1^T]
__device__ __half g_wq2h[2*CC*CC],g_wq2l[2*CC*CC]; // [s1_w2^T ; s2_w2^T]
__device__ float g_bq1[2*CC];                       // [s1_b1 ; s2_b1]
__device__ float g_bq2[2*CC];                       // [s1_b2 ; s2_b2]

static inline int cdiv(int a, int b){ return (a + b - 1) / b; }

// ---------------- mma.sync helpers (sm_80+ path; legal on plain sm_100) ----------------
__device__ __forceinline__ uint32_t smem_to_u32(const void* p) {
    uint32_t a;
    asm("{ .reg .u64 tmp; cvta.to.shared.u64 tmp, %1; cvt.u32.u64 %0, tmp; }" : "=r"(a) : "l"(p));
    return a;
}
__device__ __forceinline__ void ldmx4(uint32_t* r, uint32_t addr){
    asm volatile("ldmatrix.sync.aligned.m8n8.x4.shared.b16 {%0,%1,%2,%3}, [%4];"
        : "=r"(r[0]),"=r"(r[1]),"=r"(r[2]),"=r"(r[3]) : "r"(addr));
}
__device__ __forceinline__ void mma16816(float* c, const uint32_t* a, uint32_t b0, uint32_t b1){
    asm volatile("mma.sync.aligned.m16n8k16.row.col.f32.f16.f16.f32 "
        "{%0,%1,%2,%3}, {%4,%5,%6,%7}, {%8,%9}, {%0,%1,%2,%3};"
        : "+f"(c[0]),"+f"(c[1]),"+f"(c[2]),"+f"(c[3])
        : "r"(a[0]),"r"(a[1]),"r"(a[2]),"r"(a[3]), "r"(b0),"r"(b1));
}
__device__ __forceinline__ void cp_async16(uint32_t saddr, const void* gaddr){
    asm volatile("cp.async.cg.shared.global [%0], [%1], 16;" :: "r"(saddr), "l"(gaddr));
}
// fp16 hi/lo split: hi+lo captures ~22 mantissa bits of v
__device__ __forceinline__ void split_h(float v, __half& h, __half& l){
    h = __float2half_rn(v);
    l = __float2half_rn(v - __half2float(h));
}

// ---------- tensor-core fp16-split GEMM: C = (Ah+Al)@(Bh+Bl)^T, 3 products ----------
// Block tile 64x64, 4 warps (2m x 2n), warp tile 32x32, K-chunk 32.
// 3-stage smem pipeline + fragment double-buffer. 4 CTAs/SM (128 threads).
// If n0 >= nswitch, A pointers shift by aoff elements (fuses two GEMMs along N).
#define GM_STG 16384
#define GM_SMEM (3*16384)

template<int RELU, int WF, int WS>
__global__ void __launch_bounds__(128, 4)
gemm_mma(const __half* __restrict__ Ah, const __half* __restrict__ Al,
         const __half* __restrict__ Bh, const __half* __restrict__ Bl,
         const float* __restrict__ bias, float* __restrict__ outF,
         __half* __restrict__ outH, __half* __restrict__ outL,
         int M, int N, int K, int lda, int ldb, int nswitch, int aoff)
{
    extern __shared__ char smem[];
    uint32_t sbase = smem_to_u32(smem);
    int tid = threadIdx.x;
    int warp = tid >> 5, lane = tid & 31;
    int wm = warp & 1, wn = warp >> 1;          // 2m x 2n warps
    int m0 = blockIdx.y << 6, n0 = blockIdx.x << 6;
    if (n0 >= nswitch){ Ah += aoff; Al += aoff; }

    float acc[2][4][4];
#pragma unroll
    for (int a = 0; a < 2; a++)
#pragma unroll
        for (int b = 0; b < 4; b++)
#pragma unroll
            for (int c = 0; c < 4; c++) acc[a][b][c] = 0.f;

    int nch = K >> 5;

    auto load_chunk = [&](int ch){
        int stage = ch % 3;
        int k0 = ch << 5;
#pragma unroll
        for (int j = 0; j < 8; j++){
            int i = tid + (j << 7);             // 0..1023
            int tile = i >> 8;                  // 0:Ah 1:Al 2:Bh 3:Bl
            int rem = i & 255;
            int g = rem >> 6, r = rem & 63;
            const __half* gp;
            if (tile < 2) gp = (tile ? Al : Ah) + (long)(m0 + r)*lda + k0 + (g << 3);
            else          gp = ((tile & 1) ? Bl : Bh) + (long)(n0 + r)*ldb + k0 + (g << 3);
            uint32_t sa = sbase + stage*GM_STG + (tile << 12) + (g << 10) + (r << 4);
            cp_async16(sa, gp);
        }
        asm volatile("cp.async.commit_group;");
    };

    load_chunk(0);
    if (nch > 1) load_chunk(1);

    int ra = lane & 15;
    int ghalf = lane >> 4;

    for (int ch = 0; ch < nch; ch++){
        if (ch + 1 < nch) asm volatile("cp.async.wait_group 1;");
        else              asm volatile("cp.async.wait_group 0;");
        __syncthreads();
        if (ch + 2 < nch) load_chunk(ch + 2);

        uint32_t st = sbase + (ch % 3)*GM_STG;

        uint32_t a_h[2][2][4], a_l[2][2][4], b_h[2][2][4], b_l[2][2][4];

        auto load_frag = [&](int ks, int buf){
            int ga = (ks << 1) + ghalf;
#pragma unroll
            for (int mt = 0; mt < 2; mt++){
                int r = (wm << 5) + (mt << 4) + ra;
                uint32_t off = (uint32_t)((ga << 10) + (r << 4));
                ldmx4(a_h[buf][mt], st + off);
                ldmx4(a_l[buf][mt], st + 4096 + off);
            }
#pragma unroll
            for (int np = 0; np < 2; np++){
                int r = (wn << 5) + (np << 4) + ra;
                uint32_t off = (uint32_t)((ga << 10) + (r << 4));
                ldmx4(b_h[buf][np], st + 8192  + off);
                ldmx4(b_l[buf][np], st + 12288 + off);
            }
        };

        load_frag(0, 0);
#pragma unroll
        for (int ks = 0; ks < 2; ks++){
            int buf = ks & 1;
            if (ks == 0) load_frag(1, 1);
#pragma unroll
            for (int mt = 0; mt < 2; mt++)
#pragma unroll
                for (int nt = 0; nt < 4; nt++){
                    int np = nt >> 1, pr = nt & 1;
                    mma16816(acc[mt][nt], a_h[buf][mt], b_h[buf][np][pr], b_h[buf][np][pr+2]);
                    mma16816(acc[mt][nt], a_h[buf][mt], b_l[buf][np][pr], b_l[buf][np][pr+2]);
                    mma16816(acc[mt][nt], a_l[buf][mt], b_h[buf][np][pr], b_h[buf][np][pr+2]);
                }
        }
    }
    __syncthreads();

    // epilogue
    int col_base = n0 + (wn << 5);
    int r0 = lane >> 2;
    int cp2 = (lane & 3) << 1;
#pragma unroll
    for (int mt = 0; mt < 2; mt++){
        int row_base = m0 + (wm << 5) + (mt << 4);
#pragma unroll
        for (int i = 0; i < 2; i++){
            int m = row_base + r0 + (i << 3);
#pragma unroll
            for (int nt = 0; nt < 4; nt++){
                int col = col_base + (nt << 3) + cp2;
                float v0 = acc[mt][nt][i*2+0] + bias[col];
                float v1 = acc[mt][nt][i*2+1] + bias[col+1];
                if (RELU){ v0 = fmaxf(v0, 0.f); v1 = fmaxf(v1, 0.f); }
                if (WF){
                    float2 o; o.x = v0; o.y = v1;
                    *(float2*)&outF[(long)m*N + col] = o;
                }
                if (WS){
                    __half h0, l0, h1, l1;
                    split_h(v0, h0, l0);
                    split_h(v1, h1, l1);
                    *(__half2*)&outH[(long)m*N + col] = __halves2half2(h0, h1);
                    *(__half2*)&outL[(long)m*N + col] = __halves2half2(l0, l1);
                }
            }
        }
    }
}

// ---------------- small kernels ----------------

// PE add + fp16 split. Block per t (512); pe(t,c) computed ONCE, reused across
// the 4 vis rows and (t < WN) the 4 query rows. Same per-element math as before.
__global__ void add_pe_split_all(const float* __restrict__ xv,
                                 __half* __restrict__ xvh, __half* __restrict__ xvl,
                                 const float* __restrict__ xq,
                                 __half* __restrict__ xqh, __half* __restrict__ xql){
    int t = blockIdx.x;        // 0..511
    int c = threadIdx.x;       // 512
    int i2 = (c >> 1) << 1;
    float ang = (float)t * expf((float)i2 * -1.7988946039352293e-2f);
    float pe = (c & 1) ? cosf(ang) : sinf(ang);
#pragma unroll
    for (int b = 0; b < BB; b++){
        long o = ((long)b*TT + t)*CC + c;
        float v = xv[o] + pe;
        __half h, l; split_h(v, h, l);
        xvh[o] = h; xvl[o] = l;
    }
    if (t < WN){
#pragma unroll
        for (int b = 0; b < BB; b++){
            long o = ((long)b*WN + t)*CC + c;
            float v = xq[o] + pe;
            __half h, l; split_h(v, h, l);
            xqh[o] = h; xql[o] = l;
        }
    }
}

// batched 512x512 transpose+split (z=0..6) + bias packing (z=7)
struct TSArgs {
    const float* src[7]; __half* dh[7]; __half* dl[7];
    const float* bsrc[4]; float* bdst1; float* bdst2;
};
__global__ void transpose_split_all(TSArgs a){
    int z = blockIdx.z;
    if (z == 7){
        int idx = (blockIdx.y*16 + blockIdx.x)*256 + threadIdx.y*32 + threadIdx.x;
        if (idx < 2048){
            int seg = idx >> 9, i = idx & 511;
            float v = a.bsrc[seg][i];
            if (seg == 0) a.bdst1[i] = v;
            else if (seg == 1) a.bdst1[512 + i] = v;
            else if (seg == 2) a.bdst2[i] = v;
            else a.bdst2[512 + i] = v;
        }
        return;
    }
    const float* W = a.src[z];
    __half* Th = a.dh[z];
    __half* Tl = a.dl[z];
    __shared__ float t[32][33];
    int bx = blockIdx.x << 5, by = blockIdx.y << 5;
    int x = threadIdx.x, y = threadIdx.y;
#pragma unroll
    for (int i = 0; i < 32; i += 8) t[y+i][x] = W[(long)(by + y + i)*512 + bx + x];
    __syncthreads();
#pragma unroll
    for (int i = 0; i < 32; i += 8){
        float v = t[x][y+i];
        __half h, l; split_h(v, h, l);
        long o = (long)(bx + y + i)*512 + by + x;
        Th[o] = h; Tl[o] = l;
    }
}

// sim[b, t, w] = dot(v[b,t,:], E1[b,w,:]); E1 = EP[:, 0:512] with row stride 1024
__global__ void sim_kernel(const float* __restrict__ V, const float* __restrict__ EP,
                           float* __restrict__ SIM){
    int t = blockIdx.x, b = blockIdx.y;
    __shared__ float vrow[CC];
    int tid = threadIdx.x;
    const float* vp = &V[(b*TT + t)*CC];
    vrow[tid]       = vp[tid];
    vrow[tid + 256] = vp[tid + 256];
    __syncthreads();
    int wid = tid >> 5, lane = tid & 31;
    for (int w = wid; w < WN; w += 8){
        const float* e = &EP[(b*WN + w)*(2*CC)];
        float sum = 0.f;
        for (int c = lane; c < CC; c += 32) sum = fmaf(vrow[c], e[c], sum);
#pragma unroll
        for (int off = 16; off; off >>= 1) sum += __shfl_down_sync(0xffffffffu, sum, off);
        if (lane == 0) SIM[(b*TT + t)*WN + w] = sum;
    }
}

// two-pass chunked exclusive cumsum over t
__global__ void cumsum_part_kernel(const float* __restrict__ V, float* __restrict__ PARTS){
    int c = threadIdx.x;
    int chunk = blockIdx.x;
    int b = blockIdx.y;
    float s = 0.f;
    const float* p = &V[((b*TT) + (chunk << 6))*CC + c];
#pragma unroll 8
    for (int u = 0; u < 64; u++) s += p[u*CC];
    PARTS[(b*8 + chunk)*CC + c] = s;
}

__global__ void cumsum_write_kernel(const float* __restrict__ V, const float* __restrict__ PARTS,
                                    float* __restrict__ CUM){
    int c = threadIdx.x;
    int chunk = blockIdx.x;
    int b = blockIdx.y;
    float base = 0.f;
    for (int j = 0; j < chunk; j++) base += PARTS[(b*8 + j)*CC + c];
    int t0 = chunk << 6;
    const float* vp = &V[((b*TT) + t0)*CC + c];
    float* cp = &CUM[((b*(TT+1)) + t0)*CC + c];
    float acc = base;
#pragma unroll 8
    for (int u = 0; u < 64; u++){
        cp[u*CC] = acc;
        acc += vp[u*CC];
    }
    if (chunk == 7) cp[64*CC] = acc;
}

// fused labels (warp-0 argmax) + split-A row build; ONE window per launch
__global__ void labelbuild_kernel(const float* __restrict__ SIM, const float* __restrict__ CUM,
                                  const float* __restrict__ EP,
                                  __half* __restrict__ Aho, __half* __restrict__ Alo,
                                  int nt0, int s){
    int row = blockIdx.x;                      // 0..BB*nt0-1
    int b = row / nt0, t0 = row % nt0;
    __shared__ int slab;
    int tid = threadIdx.x;                     // 512
    if (tid < 32){
        const float* sp = &SIM[(b*TT + t0)*WN + tid];
        float sum = 0.f;
        for (int u = 0; u < s; u++) sum += sp[u*WN];
        float best = sum; int bi = tid;
#pragma unroll
        for (int off = 16; off; off >>= 1){
            float ov = __shfl_down_sync(0xffffffffu, best, off);
            int   oi = __shfl_down_sync(0xffffffffu, bi,   off);
            if (ov > best || (ov == best && oi < bi)){ best = ov; bi = oi; }
        }
        if (tid == 0) slab = bi;
    }
    __syncthreads();
    int lab = slab;
    int c = tid;
    float vu = (CUM[(b*(TT+1) + t0 + s)*CC + c] - CUM[(b*(TT+1) + t0)*CC + c]) * (1.f/(float)s);
    float v = vu * EP[(b*WN + lab)*(2*CC) + CC + c];
    __half h, l; split_h(v, h, l);
    Aho[(long)row*CC + c] = h;
    Alo[(long)row*CC + c] = l;
}

// fused adaptive max pool + seg head; z = window (Md rows at 0 / AOFF1)
struct SegArgs { const float* sw[2]; const float* sb[2]; };
__global__ void pool_seg_kernel(const int* __restrict__ vid_len, const float* __restrict__ Md,
                                float* __restrict__ POOL, SegArgs a, float* __restrict__ out){
    int i = blockIdx.x, b = blockIdx.y, z = blockIdx.z;
    int d = threadIdx.x;                       // 512
    int s   = z ? 16 : 8;
    int nt0 = TT - s + 1;
    const float* Mw = Md + (long)(z ? AOFF1 : 0)*DD;
    float* PO = POOL + (long)z*BB*PP*DD;
    int Lin = vid_len[b] * 8;
    if (Lin < 1) Lin = 1;
    int start = (i * Lin) >> 6;
    int end   = ((i + 1) * Lin + 63) >> 6;
    const float* base = Mw + (long)b*nt0*DD + d;
    float m = -3.402823466e38f;
    for (int r = start; r < end; r++){
        int t0 = (r >> 3) + (r & 7) * s;
        float v = base[(long)t0*DD];
        m = fmaxf(m, v);
    }
    PO[(b*PP + i)*DD + d] = m;

    // seg head: dot over d of pooled row with sw[:,0] / sw[:,1]
    const float* sw = a.sw[z];
    float a0 = m * sw[2*d];
    float a1 = m * sw[2*d + 1];
    int lane = d & 31, wid = d >> 5;
#pragma unroll
    for (int off = 16; off; off >>= 1){
        a0 += __shfl_down_sync(0xffffffffu, a0, off);
        a1 += __shfl_down_sync(0xffffffffu, a1, off);
    }
    __shared__ float s0[16], s1[16];
    if (lane == 0){ s0[wid] = a0; s1[wid] = a1; }
    __syncthreads();
    if (d == 0){
        const float* sb = a.sb[z];
        float r0 = 0.f, r1 = 0.f;
#pragma unroll
        for (int w = 0; w < 16; w++){ r0 += s0[w]; r1 += s1[w]; }
        int obase = z ? 1024 : 0;
        out[obase + b*128 + i]      = r0 + sb[0];
        out[obase + b*128 + 64 + i] = r1 + sb[1];
    }
}

// st/en heads: 4 matrices x 64 k-splits in one launch
#define KSPLIT 64
struct VHArgs { const float* W[4]; };
__global__ void vechead_partial(VHArgs a, const float* __restrict__ POOL,
                                float* __restrict__ PART){
    int ks = blockIdx.x;
    int mat = blockIdx.y;                      // 0=st0 1=en0 2=st1 3=en1
    const float* W = a.W[mat];
    const float* PO = POOL + (long)(mat >> 1)*BB*PP*DD;
    int wid = threadIdx.x >> 5, lane = threadIdx.x & 31;
    float acc[4][2] = {{0.f,0.f},{0.f,0.f},{0.f,0.f},{0.f,0.f}};
    int kbase = ks * 512;
    for (int kk = wid; kk < 512; kk += 8){
        int k = kbase + kk;
        float w0 = W[k*64 + lane];
        float w1 = W[k*64 + 32 + lane];
        int p = k & 63, d = k >> 6;
#pragma unroll
        for (int b = 0; b < 4; b++){
            float v = PO[(b*PP + p)*DD + d];
            acc[b][0] = fmaf(v, w0, acc[b][0]);
            acc[b][1] = fmaf(v, w1, acc[b][1]);
        }
    }
    __shared__ float red[8][4][64];
#pragma unroll
    for (int b = 0; b < 4; b++){
        red[wid][b][lane]      = acc[b][0];
        red[wid][b][lane + 32] = acc[b][1];
    }
    __syncthreads();
    int o = threadIdx.x;
    int b = o >> 6, p = o & 63;
    float s = 0.f;
#pragma unroll
    for (int w = 0; w < 8; w++) s += red[w][b][p];
    PART[((mat*KSPLIT + ks)*4 + b)*64 + p] = s;
}

__global__ void vechead_final(const float* __restrict__ PART,
                              const float* __restrict__ b0, const float* __restrict__ b1,
                              const float* __restrict__ b2, const float* __restrict__ b3,
                              float* __restrict__ out){
    int o = blockIdx.x * 256 + threadIdx.x;
    if (o >= 4*4*64) return;
    int mat = o >> 8, rem = o & 255;
    int b = rem >> 6, p = rem & 63;
    float s = 0.f;
#pragma unroll
    for (int ks = 0; ks < KSPLIT; ks++) s += PART[((mat*KSPLIT + ks)*4 + b)*64 + p];
    const float* bias = (mat == 0) ? b0 : (mat == 1) ? b1 : (mat == 2) ? b2 : b3;
    int off = (mat == 0) ? 512 : (mat == 1) ? 768 : (mat == 2) ? 1536 : 1792;
    out[off + b*64 + p] = s + bias[p];
}

// L2 warm-up for st/en weights (32MB); sums into write-only scratch
struct PFArgs { const float* W[4]; };
__global__ void prefetch_kernel(PFArgs a, float* __restrict__ sink){
    float s = 0.f;
    int tid = threadIdx.x;
    const int n4 = 32768*64/4;                 // float4 per matrix
#pragma unroll
    for (int m = 0; m < 4; m++){
        const float4* p = (const float4*)a.W[m];
        for (int i = blockIdx.x*256 + tid; i < n4; i += 256*256){
            float4 v = p[i];
            s += v.x + v.y + v.z + v.w;
        }
    }
    __shared__ float red[256];
    red[tid] = s;
    __syncthreads();
    if (tid == 0){
        float t = 0.f;
        for (int i = 0; i < 256; i++) t += red[i];
        sink[blockIdx.x] = t;
    }
}

// ---------------- launcher ----------------
extern "C" void kernel_launch(void* const* d_in, const int* in_sizes, int n_in,
                              void* d_out, int out_size){
    const float* vis     = (const float*)d_in[0];
    const float* qry     = (const float*)d_in[1];
    const int*   vlen    = (const int*)  d_in[2];
    const float* vid_w1  = (const float*)d_in[3];
    const float* vid_b1  = (const float*)d_in[4];
    const float* vid_w2  = (const float*)d_in[5];
    const float* vid_b2  = (const float*)d_in[6];
    const float* s1_w1   = (const float*)d_in[7];
    const float* s1_b1   = (const float*)d_in[8];
    const float* s1_w2   = (const float*)d_in[9];
    const float* s1_b2   = (const float*)d_in[10];
    const float* s2_w1   = (const float*)d_in[11];
    const float* s2_b1   = (const float*)d_in[12];
    const float* s2_w2   = (const float*)d_in[13];
    const float* s2_b2   = (const float*)d_in[14];
    const float* proj_w  = (const float*)d_in[15];
    const float* proj_b  = (const float*)d_in[16];
    const float* st_w0   = (const float*)d_in[17];
    const float* st_b0   = (const float*)d_in[18];
    const float* en_w0   = (const float*)d_in[19];
    const float* en_b0   = (const float*)d_in[20];
    const float* sg_w0   = (const float*)d_in[21];
    const float* sg_b0   = (const float*)d_in[22];
    const float* st_w1   = (const float*)d_in[23];
    const float* st_b1   = (const float*)d_in[24];
    const float* en_w1   = (const float*)d_in[25];
    const float* en_b1   = (const float*)d_in[26];
    const float* sg_w1   = (const float*)d_in[27];
    const float* sg_b1   = (const float*)d_in[28];
    float* out = (float*)d_out;

    __half *Xvh, *Xvl, *Hh, *Hl, *Xqh, *Xql, *Hqh, *Hql, *Ah, *Al;
    __half *w1h, *w1l, *w2h, *w2l, *pwh, *pwl, *wq1h, *wq1l, *wq2h, *wq2l;
    float *V, *EP, *SIM, *CUM, *PARTS, *Md, *POOL, *PART, *BQ1, *BQ2, *SINK;
    cudaGetSymbolAddress((void**)&Xvh, g_Xvh);
    cudaGetSymbolAddress((void**)&Xvl, g_Xvl);
    cudaGetSymbolAddress((void**)&Hh,  g_Hh);
    cudaGetSymbolAddress((void**)&Hl,  g_Hl);
    cudaGetSymbolAddress((void**)&V,   g_V);
    cudaGetSymbolAddress((void**)&Xqh, g_Xqh);
    cudaGetSymbolAddress((void**)&Xql, g_Xql);
    cudaGetSymbolAddress((void**)&Hqh, g_Hqh);
    cudaGetSymbolAddress((void**)&Hql, g_Hql);
    cudaGetSymbolAddress((void**)&EP,  g_ep);
    cudaGetSymbolAddress((void**)&SIM, g_sim);
    cudaGetSymbolAddress((void**)&CUM, g_cum);
    cudaGetSymbolAddress((void**)&PARTS, g_parts);
    cudaGetSymbolAddress((void**)&Ah,  g_Ah);
    cudaGetSymbolAddress((void**)&Al,  g_Al);
    cudaGetSymbolAddress((void**)&Md,  g_Md);
    cudaGetSymbolAddress((void**)&POOL,g_pool);
    cudaGetSymbolAddress((void**)&PART,g_part);
    cudaGetSymbolAddress((void**)&SINK,g_dummy);
    cudaGetSymbolAddress((void**)&w1h, g_w1h);
    cudaGetSymbolAddress((void**)&w1l, g_w1l);
    cudaGetSymbolAddress((void**)&w2h, g_w2h);
    cudaGetSymbolAddress((void**)&w2l, g_w2l);
    cudaGetSymbolAddress((void**)&pwh, g_pwh);
    cudaGetSymbolAddress((void**)&pwl, g_pwl);
    cudaGetSymbolAddress((void**)&wq1h, g_wq1h);
    cudaGetSymbolAddress((void**)&wq1l, g_wq1l);
    cudaGetSymbolAddress((void**)&wq2h, g_wq2h);
    cudaGetSymbolAddress((void**)&wq2l, g_wq2l);
    cudaGetSymbolAddress((void**)&BQ1, g_bq1);
    cudaGetSymbolAddress((void**)&BQ2, g_bq2);

    cudaFuncSetAttribute(gemm_mma<1,0,1>, cudaFuncAttributeMaxDynamicSharedMemorySize, GM_SMEM);
    cudaFuncSetAttribute(gemm_mma<0,1,0>, cudaFuncAttributeMaxDynamicSharedMemorySize, GM_SMEM);

    // one-time aux stream + events (resources only; work identical each call)
    static cudaStream_t aux = nullptr;
    static cudaEvent_t evF, evT, evPE, evV, evS, evC, evL1, evPF;
    if (aux == nullptr){
        cudaStreamCreateWithFlags(&aux, cudaStreamNonBlocking);
        cudaEventCreateWithFlags(&evF,  cudaEventDisableTiming);
        cudaEventCreateWithFlags(&evT,  cudaEventDisableTiming);
        cudaEventCreateWithFlags(&evPE, cudaEventDisableTiming);
        cudaEventCreateWithFlags(&evV,  cudaEventDisableTiming);
        cudaEventCreateWithFlags(&evS,  cudaEventDisableTiming);
        cudaEventCreateWithFlags(&evC,  cudaEventDisableTiming);
        cudaEventCreateWithFlags(&evL1, cudaEventDisableTiming);
        cudaEventCreateWithFlags(&evPF, cudaEventDisableTiming);
    }

    const int NSW_NONE = 1 << 30;

    // ---- fork at top ----
    cudaEventRecord(evF, 0);
    cudaStreamWaitEvent(aux, evF, 0);

    // aux: weight transposes + bias packs (z=7) — overlaps PE-add on main
    TSArgs ts;
    ts.src[0] = vid_w1; ts.dh[0] = w1h;  ts.dl[0] = w1l;
    ts.src[1] = vid_w2; ts.dh[1] = w2h;  ts.dl[1] = w2l;
    ts.src[2] = proj_w; ts.dh[2] = pwh;  ts.dl[2] = pwl;
    ts.src[3] = s1_w1;  ts.dh[3] = wq1h;           ts.dl[3] = wq1l;
    ts.src[4] = s2_w1;  ts.dh[4] = wq1h + 512*512; ts.dl[4] = wq1l + 512*512;
    ts.src[5] = s1_w2;  ts.dh[5] = wq2h;           ts.dl[5] = wq2l;
    ts.src[6] = s2_w2;  ts.dh[6] = wq2h + 512*512; ts.dl[6] = wq2l + 512*512;
    ts.bsrc[0] = s1_b1; ts.bsrc[1] = s2_b1; ts.bsrc[2] = s1_b2; ts.bsrc[3] = s2_b2;
    ts.bdst1 = BQ1; ts.bdst2 = BQ2;
    transpose_split_all<<<dim3(16,16,8), dim3(32,8), 0, aux>>>(ts);
    cudaEventRecord(evT, aux);

    // main: PE add + split (vis & query; pe computed once per (t,c))
    add_pe_split_all<<<TT, CC>>>(vis, Xvh, Xvl, qry, Xqh, Xql);
    cudaEventRecord(evPE, 0);
    cudaStreamWaitEvent(0, evT, 0);            // vid weights ready

    // aux: enc chain (Xq from PE; weights already on aux timeline)
    cudaStreamWaitEvent(aux, evPE, 0);
    gemm_mma<1,0,1><<<dim3(2*CC/64, BB*WN/64), 128, GM_SMEM, aux>>>(
        Xqh, Xql, wq1h, wq1l, BQ1, nullptr, Hqh, Hql, BB*WN, 2*CC, CC, CC, CC, NSW_NONE, 0);
    gemm_mma<0,1,0><<<dim3(2*CC/64, BB*WN/64), 128, GM_SMEM, aux>>>(
        Hqh, Hql, wq2h, wq2l, BQ2, EP, nullptr, nullptr, BB*WN, 2*CC, CC, 2*CC, CC, CC, CC);

    // main: vid MLP
    gemm_mma<1,0,1><<<dim3(CC/64, BB*TT/64), 128, GM_SMEM>>>(
        Xvh, Xvl, w1h, w1l, vid_b1, nullptr, Hh, Hl, BB*TT, CC, CC, CC, CC, NSW_NONE, 0);
    gemm_mma<0,1,0><<<dim3(CC/64, BB*TT/64), 128, GM_SMEM>>>(
        Hh, Hl, w2h, w2l, vid_b2, V, nullptr, nullptr, BB*TT, CC, CC, CC, CC, NSW_NONE, 0);
    cudaEventRecord(evV, 0);                   // V ready

    // aux: sim (needs V + EP), concurrent with cumsum on main
    cudaStreamWaitEvent(aux, evV, 0);
    sim_kernel<<<dim3(TT, BB), 256, 0, aux>>>(V, EP, SIM);
    cudaEventRecord(evS, aux);

    // main: chunked prefix sums of v
    cumsum_part_kernel<<<dim3(8, BB), 512>>>(V, PARTS);
    cumsum_write_kernel<<<dim3(8, BB), 512>>>(V, PARTS, CUM);
    cudaEventRecord(evC, 0);

    // aux: labelbuild window 1, then L2 prefetch of head weights (under proj)
    cudaStreamWaitEvent(aux, evC, 0);
    labelbuild_kernel<<<ROWS1, CC, 0, aux>>>(SIM, CUM, EP,
        Ah + (long)AOFF1*CC, Al + (long)AOFF1*CC, NT0_W1, 16);
    cudaEventRecord(evL1, aux);
    PFArgs pf;
    pf.W[0] = st_w0; pf.W[1] = en_w0; pf.W[2] = st_w1; pf.W[3] = en_w1;
    prefetch_kernel<<<256, 256, 0, aux>>>(pf, SINK);
    cudaEventRecord(evPF, aux);

    // main: labelbuild window 0, join lb_w1, ONE merged projection GEMM
    cudaStreamWaitEvent(0, evS, 0);
    labelbuild_kernel<<<ROWS0, CC>>>(SIM, CUM, EP, Ah, Al, NT0_W0, 8);
    cudaStreamWaitEvent(0, evL1, 0);
    gemm_mma<0,1,0><<<dim3(DD/64, 4096/64), 128, GM_SMEM>>>(
        Ah, Al, pwh, pwl, proj_b, Md, nullptr, nullptr, 4096, DD, CC, CC, CC, NSW_NONE, 0);

    // fused pool + seg (both windows), then vechead
    SegArgs sa;
    sa.sw[0] = sg_w0; sa.sb[0] = sg_b0;
    sa.sw[1] = sg_w1; sa.sb[1] = sg_b1;
    pool_seg_kernel<<<dim3(PP, BB, 2), DD>>>(vlen, Md, POOL, sa, out);

    VHArgs vh;
    vh.W[0] = st_w0; vh.W[1] = en_w0; vh.W[2] = st_w1; vh.W[3] = en_w1;
    vechead_partial<<<dim3(KSPLIT, 4), 256>>>(vh, POOL, PART);
    cudaStreamWaitEvent(0, evPF, 0);           // join prefetch (long since done)
    vechead_final<<<4, 256>>>(PART, st_b0, en_b0, st_b1, en_b1, out);
}

// round 16
// speedup vs baseline: 1.3171x; 1.0748x over previous
#include <cuda_runtime.h>
#include <cuda_fp16.h>
#include <math.h>
#include <stdint.h>

// Problem constants (fixed shapes)
#define BB 4
#define TT 512
#define CC 512
#define WN 32
#define DD 512
#define PP 64

#define NT0_W0 (TT-8+1)          // 505
#define NT0_W1 (TT-16+1)         // 497
#define ROWS0 (BB*NT0_W0)        // 2020
#define ROWS1 (BB*NT0_W1)        // 1988
#define AOFF1 2048               // window-1 A/Md row offset (pad rows stay zero)

// ---------------- scratch (static device globals; no allocation) ----------------
__device__ __half g_Xvh[BB*TT*CC], g_Xvl[BB*TT*CC];
__device__ __half g_Hh [BB*TT*CC], g_Hl [BB*TT*CC];
__device__ float g_V  [BB*TT*CC];
__device__ __half g_Xqh[BB*WN*CC], g_Xql[BB*WN*CC];
__device__ __half g_Hqh[BB*WN*2*CC], g_Hql[BB*WN*2*CC];   // [128, 1024]
__device__ float g_ep [BB*WN*2*CC];                        // [128, 1024] = [E1 | E2]
__device__ float g_sim[BB*TT*WN];
__device__ float g_cum[BB*(TT+1)*CC];
__device__ float g_parts[BB*8*CC];
__device__ __half g_Ah[4096*CC], g_Al[4096*CC];   // zero-init; pad rows never written
__device__ float g_Md [4096*DD];
__device__ float g_pool[2*BB*PP*DD];               // per-window buffers
__device__ float g_part[4*64*BB*PP];
__device__ float g_dummy[256];                     // prefetch sink (never read)
__device__ __half g_w1h[CC*CC],   g_w1l[CC*CC];    // vid_w1^T
__device__ __half g_w2h[CC*CC],   g_w2l[CC*CC];    // vid_w2^T
__device__ __half g_pwh[CC*DD],   g_pwl[CC*DD];    // proj_w^T
__device__ __half g_wq1h[2*CC*CC],g_wq1l[2*CC*CC]; // [s1_w1^T ; s2_w1^T]
__device__ __half g_wq2h[2*CC*CC],g_wq2l[2*CC*CC]; // [s1_w2^T ; s2_w2^T]
__device__ float g_bq1[2*CC];                       // [s1_b1 ; s2_b1]
__device__ float g_bq2[2*CC];                       // [s1_b2 ; s2_b2]

static inline int cdiv(int a, int b){ return (a + b - 1) / b; }

// ---------------- mma.sync helpers (sm_80+ path; legal on plain sm_100) ----------------
__device__ __forceinline__ uint32_t smem_to_u32(const void* p) {
    uint32_t a;
    asm("{ .reg .u64 tmp; cvta.to.shared.u64 tmp, %1; cvt.u32.u64 %0, tmp; }" : "=r"(a) : "l"(p));
    return a;
}
__device__ __forceinline__ void ldmx4(uint32_t* r, uint32_t addr){
    asm volatile("ldmatrix.sync.aligned.m8n8.x4.shared.b16 {%0,%1,%2,%3}, [%4];"
        : "=r"(r[0]),"=r"(r[1]),"=r"(r[2]),"=r"(r[3]) : "r"(addr));
}
__device__ __forceinline__ void mma16816(float* c, const uint32_t* a, uint32_t b0, uint32_t b1){
    asm volatile("mma.sync.aligned.m16n8k16.row.col.f32.f16.f16.f32 "
        "{%0,%1,%2,%3}, {%4,%5,%6,%7}, {%8,%9}, {%0,%1,%2,%3};"
        : "+f"(c[0]),"+f"(c[1]),"+f"(c[2]),"+f"(c[3])
        : "r"(a[0]),"r"(a[1]),"r"(a[2]),"r"(a[3]), "r"(b0),"r"(b1));
}
__device__ __forceinline__ void cp_async16(uint32_t saddr, const void* gaddr){
    asm volatile("cp.async.cg.shared.global [%0], [%1], 16;" :: "r"(saddr), "l"(gaddr));
}
// fp16 hi/lo split: hi+lo captures ~22 mantissa bits of v
__device__ __forceinline__ void split_h(float v, __half& h, __half& l){
    h = __float2half_rn(v);
    l = __float2half_rn(v - __half2float(h));
}

// ---------- tensor-core fp16-split GEMM: C = (Ah[+Al])@(Bh+Bl)^T ----------
// PROD3=1: 3 products (err ~2^-22); PROD3=0: 2 products Ah·(Bh+Bl), skips the
// Al tile load/ldmatrix/mma entirely (err ~2^-12, used only post-argmax).
// Block tile 64x64, 4 warps (2m x 2n), warp tile 32x32, K-chunk 32.
// 3-stage smem pipeline + fragment double-buffer. 4 CTAs/SM (128 threads).
// If n0 >= nswitch, A pointers shift by aoff elements (fuses two GEMMs along N).
#define GM_STG 16384
#define GM_SMEM (3*16384)

template<int RELU, int WF, int WS, int PROD3>
__global__ void __launch_bounds__(128, 4)
gemm_mma(const __half* __restrict__ Ah, const __half* __restrict__ Al,
         const __half* __restrict__ Bh, const __half* __restrict__ Bl,
         const float* __restrict__ bias, float* __restrict__ outF,
         __half* __restrict__ outH, __half* __restrict__ outL,
         int M, int N, int K, int lda, int ldb, int nswitch, int aoff)
{
    extern __shared__ char smem[];
    uint32_t sbase = smem_to_u32(smem);
    int tid = threadIdx.x;
    int warp = tid >> 5, lane = tid & 31;
    int wm = warp & 1, wn = warp >> 1;          // 2m x 2n warps
    int m0 = blockIdx.y << 6, n0 = blockIdx.x << 6;
    if (n0 >= nswitch){ Ah += aoff; Al += aoff; }

    float acc[2][4][4];
#pragma unroll
    for (int a = 0; a < 2; a++)
#pragma unroll
        for (int b = 0; b < 4; b++)
#pragma unroll
            for (int c = 0; c < 4; c++) acc[a][b][c] = 0.f;

    int nch = K >> 5;

    auto load_chunk = [&](int ch){
        int stage = ch % 3;
        int k0 = ch << 5;
#pragma unroll
        for (int j = 0; j < 8; j++){
            int i = tid + (j << 7);             // 0..1023
            int tile = i >> 8;                  // 0:Ah 1:Al 2:Bh 3:Bl
            if (!PROD3 && tile == 1) continue;  // 2-product: Al never read
            int rem = i & 255;
            int g = rem >> 6, r = rem & 63;
            const __half* gp;
            if (tile < 2) gp = (tile ? Al : Ah) + (long)(m0 + r)*lda + k0 + (g << 3);
            else          gp = ((tile & 1) ? Bl : Bh) + (long)(n0 + r)*ldb + k0 + (g << 3);
            uint32_t sa = sbase + stage*GM_STG + (tile << 12) + (g << 10) + (r << 4);
            cp_async16(sa, gp);
        }
        asm volatile("cp.async.commit_group;");
    };

    load_chunk(0);
    if (nch > 1) load_chunk(1);

    int ra = lane & 15;
    int ghalf = lane >> 4;

    for (int ch = 0; ch < nch; ch++){
        if (ch + 1 < nch) asm volatile("cp.async.wait_group 1;");
        else              asm volatile("cp.async.wait_group 0;");
        __syncthreads();
        if (ch + 2 < nch) load_chunk(ch + 2);

        uint32_t st = sbase + (ch % 3)*GM_STG;

        uint32_t a_h[2][2][4], a_l[2][2][4], b_h[2][2][4], b_l[2][2][4];

        auto load_frag = [&](int ks, int buf){
            int ga = (ks << 1) + ghalf;
#pragma unroll
            for (int mt = 0; mt < 2; mt++){
                int r = (wm << 5) + (mt << 4) + ra;
                uint32_t off = (uint32_t)((ga << 10) + (r << 4));
                ldmx4(a_h[buf][mt], st + off);
                if (PROD3) ldmx4(a_l[buf][mt], st + 4096 + off);
            }
#pragma unroll
            for (int np = 0; np < 2; np++){
                int r = (wn << 5) + (np << 4) + ra;
                uint32_t off = (uint32_t)((ga << 10) + (r << 4));
                ldmx4(b_h[buf][np], st + 8192  + off);
                ldmx4(b_l[buf][np], st + 12288 + off);
            }
        };

        load_frag(0, 0);
#pragma unroll
        for (int ks = 0; ks < 2; ks++){
            int buf = ks & 1;
            if (ks == 0) load_frag(1, 1);
#pragma unroll
            for (int mt = 0; mt < 2; mt++)
#pragma unroll
                for (int nt = 0; nt < 4; nt++){
                    int np = nt >> 1, pr = nt & 1;
                    mma16816(acc[mt][nt], a_h[buf][mt], b_h[buf][np][pr], b_h[buf][np][pr+2]);
                    mma16816(acc[mt][nt], a_h[buf][mt], b_l[buf][np][pr], b_l[buf][np][pr+2]);
                    if (PROD3)
                        mma16816(acc[mt][nt], a_l[buf][mt], b_h[buf][np][pr], b_h[buf][np][pr+2]);
                }
        }
    }
    __syncthreads();

    // epilogue
    int col_base = n0 + (wn << 5);
    int r0 = lane >> 2;
    int cp2 = (lane & 3) << 1;
#pragma unroll
    for (int mt = 0; mt < 2; mt++){
        int row_base = m0 + (wm << 5) + (mt << 4);
#pragma unroll
        for (int i = 0; i < 2; i++){
            int m = row_base + r0 + (i << 3);
#pragma unroll
            for (int nt = 0; nt < 4; nt++){
                int col = col_base + (nt << 3) + cp2;
                float v0 = acc[mt][nt][i*2+0] + bias[col];
                float v1 = acc[mt][nt][i*2+1] + bias[col+1];
                if (RELU){ v0 = fmaxf(v0, 0.f); v1 = fmaxf(v1, 0.f); }
                if (WF){
                    float2 o; o.x = v0; o.y = v1;
                    *(float2*)&outF[(long)m*N + col] = o;
                }
                if (WS){
                    __half h0, l0, h1, l1;
                    split_h(v0, h0, l0);
                    split_h(v1, h1, l1);
                    *(__half2*)&outH[(long)m*N + col] = __halves2half2(h0, h1);
                    *(__half2*)&outL[(long)m*N + col] = __halves2half2(l0, l1);
                }
            }
        }
    }
}

// ---------------- small kernels ----------------

// PE add + fp16 split. Block per t (512); pe(t,c) computed ONCE, reused across
// the 4 vis rows and (t < WN) the 4 query rows.
__global__ void add_pe_split_all(const float* __restrict__ xv,
                                 __half* __restrict__ xvh, __half* __restrict__ xvl,
                                 const float* __restrict__ xq,
                                 __half* __restrict__ xqh, __half* __restrict__ xql){
    int t = blockIdx.x;        // 0..511
    int c = threadIdx.x;       // 512
    int i2 = (c >> 1) << 1;
    float ang = (float)t * expf((float)i2 * -1.7988946039352293e-2f);
    float pe = (c & 1) ? cosf(ang) : sinf(ang);
#pragma unroll
    for (int b = 0; b < BB; b++){
        long o = ((long)b*TT + t)*CC + c;
        float v = xv[o] + pe;
        __half h, l; split_h(v, h, l);
        xvh[o] = h; xvl[o] = l;
    }
    if (t < WN){
#pragma unroll
        for (int b = 0; b < BB; b++){
            long o = ((long)b*WN + t)*CC + c;
            float v = xq[o] + pe;
            __half h, l; split_h(v, h, l);
            xqh[o] = h; xql[o] = l;
        }
    }
}

// batched 512x512 transpose+split (z=0..6) + bias packing (z=7)
struct TSArgs {
    const float* src[7]; __half* dh[7]; __half* dl[7];
    const float* bsrc[4]; float* bdst1; float* bdst2;
};
__global__ void transpose_split_all(TSArgs a){
    int z = blockIdx.z;
    if (z == 7){
        int idx = (blockIdx.y*16 + blockIdx.x)*256 + threadIdx.y*32 + threadIdx.x;
        if (idx < 2048){
            int seg = idx >> 9, i = idx & 511;
            float v = a.bsrc[seg][i];
            if (seg == 0) a.bdst1[i] = v;
            else if (seg == 1) a.bdst1[512 + i] = v;
            else if (seg == 2) a.bdst2[i] = v;
            else a.bdst2[512 + i] = v;
        }
        return;
    }
    const float* W = a.src[z];
    __half* Th = a.dh[z];
    __half* Tl = a.dl[z];
    __shared__ float t[32][33];
    int bx = blockIdx.x << 5, by = blockIdx.y << 5;
    int x = threadIdx.x, y = threadIdx.y;
#pragma unroll
    for (int i = 0; i < 32; i += 8) t[y+i][x] = W[(long)(by + y + i)*512 + bx + x];
    __syncthreads();
#pragma unroll
    for (int i = 0; i < 32; i += 8){
        float v = t[x][y+i];
        __half h, l; split_h(v, h, l);
        long o = (long)(bx + y + i)*512 + by + x;
        Th[o] = h; Tl[o] = l;
    }
}

// sim[b, t, w] = dot(v[b,t,:], E1[b,w,:]); E1 = EP[:, 0:512] with row stride 1024
__global__ void sim_kernel(const float* __restrict__ V, const float* __restrict__ EP,
                           float* __restrict__ SIM){
    int t = blockIdx.x, b = blockIdx.y;
    __shared__ float vrow[CC];
    int tid = threadIdx.x;
    const float* vp = &V[(b*TT + t)*CC];
    vrow[tid]       = vp[tid];
    vrow[tid + 256] = vp[tid + 256];
    __syncthreads();
    int wid = tid >> 5, lane = tid & 31;
    for (int w = wid; w < WN; w += 8){
        const float* e = &EP[(b*WN + w)*(2*CC)];
        float sum = 0.f;
        for (int c = lane; c < CC; c += 32) sum = fmaf(vrow[c], e[c], sum);
#pragma unroll
        for (int off = 16; off; off >>= 1) sum += __shfl_down_sync(0xffffffffu, sum, off);
        if (lane == 0) SIM[(b*TT + t)*WN + w] = sum;
    }
}

// two-pass chunked exclusive cumsum over t
__global__ void cumsum_part_kernel(const float* __restrict__ V, float* __restrict__ PARTS){
    int c = threadIdx.x;
    int chunk = blockIdx.x;
    int b = blockIdx.y;
    float s = 0.f;
    const float* p = &V[((b*TT) + (chunk << 6))*CC + c];
#pragma unroll 8
    for (int u = 0; u < 64; u++) s += p[u*CC];
    PARTS[(b*8 + chunk)*CC + c] = s;
}

__global__ void cumsum_write_kernel(const float* __restrict__ V, const float* __restrict__ PARTS,
                                    float* __restrict__ CUM){
    int c = threadIdx.x;
    int chunk = blockIdx.x;
    int b = blockIdx.y;
    float base = 0.f;
    for (int j = 0; j < chunk; j++) base += PARTS[(b*8 + j)*CC + c];
    int t0 = chunk << 6;
    const float* vp = &V[((b*TT) + t0)*CC + c];
    float* cp = &CUM[((b*(TT+1)) + t0)*CC + c];
    float acc = base;
#pragma unroll 8
    for (int u = 0; u < 64; u++){
        cp[u*CC] = acc;
        acc += vp[u*CC];
    }
    if (chunk == 7) cp[64*CC] = acc;
}

// fused labels (warp-0 argmax) + split-A row build; ONE window per launch
__global__ void labelbuild_kernel(const float* __restrict__ SIM, const float* __restrict__ CUM,
                                  const float* __restrict__ EP,
                                  __half* __restrict__ Aho, __half* __restrict__ Alo,
                                  int nt0, int s){
    int row = blockIdx.x;                      // 0..BB*nt0-1
    int b = row / nt0, t0 = row % nt0;
    __shared__ int slab;
    int tid = threadIdx.x;                     // 512
    if (tid < 32){
        const float* sp = &SIM[(b*TT + t0)*WN + tid];
        float sum = 0.f;
        for (int u = 0; u < s; u++) sum += sp[u*WN];
        float best = sum; int bi = tid;
#pragma unroll
        for (int off = 16; off; off >>= 1){
            float ov = __shfl_down_sync(0xffffffffu, best, off);
            int   oi = __shfl_down_sync(0xffffffffu, bi,   off);
            if (ov > best || (ov == best && oi < bi)){ best = ov; bi = oi; }
        }
        if (tid == 0) slab = bi;
    }
    __syncthreads();
    int lab = slab;
    int c = tid;
    float vu = (CUM[(b*(TT+1) + t0 + s)*CC + c] - CUM[(b*(TT+1) + t0)*CC + c]) * (1.f/(float)s);
    float v = vu * EP[(b*WN + lab)*(2*CC) + CC + c];
    __half h, l; split_h(v, h, l);
    Aho[(long)row*CC + c] = h;
    Alo[(long)row*CC + c] = l;
}

// fused adaptive max pool + seg head; z = window (Md rows at 0 / AOFF1)
struct SegArgs { const float* sw[2]; const float* sb[2]; };
__global__ void pool_seg_kernel(const int* __restrict__ vid_len, const float* __restrict__ Md,
                                float* __restrict__ POOL, SegArgs a, float* __restrict__ out){
    int i = blockIdx.x, b = blockIdx.y, z = blockIdx.z;
    int d = threadIdx.x;                       // 512
    int s   = z ? 16 : 8;
    int nt0 = TT - s + 1;
    const float* Mw = Md + (long)(z ? AOFF1 : 0)*DD;
    float* PO = POOL + (long)z*BB*PP*DD;
    int Lin = vid_len[b] * 8;
    if (Lin < 1) Lin = 1;
    int start = (i * Lin) >> 6;
    int end   = ((i + 1) * Lin + 63) >> 6;
    const float* base = Mw + (long)b*nt0*DD + d;
    float m = -3.402823466e38f;
    for (int r = start; r < end; r++){
        int t0 = (r >> 3) + (r & 7) * s;
        float v = base[(long)t0*DD];
        m = fmaxf(m, v);
    }
    PO[(b*PP + i)*DD + d] = m;

    // seg head: dot over d of pooled row with sw[:,0] / sw[:,1]
    const float* sw = a.sw[z];
    float a0 = m * sw[2*d];
    float a1 = m * sw[2*d + 1];
    int lane = d & 31, wid = d >> 5;
#pragma unroll
    for (int off = 16; off; off >>= 1){
        a0 += __shfl_down_sync(0xffffffffu, a0, off);
        a1 += __shfl_down_sync(0xffffffffu, a1, off);
    }
    __shared__ float s0[16], s1[16];
    if (lane == 0){ s0[wid] = a0; s1[wid] = a1; }
    __syncthreads();
    if (d == 0){
        const float* sb = a.sb[z];
        float r0 = 0.f, r1 = 0.f;
#pragma unroll
        for (int w = 0; w < 16; w++){ r0 += s0[w]; r1 += s1[w]; }
        int obase = z ? 1024 : 0;
        out[obase + b*128 + i]      = r0 + sb[0];
        out[obase + b*128 + 64 + i] = r1 + sb[1];
    }
}

// st/en heads: 4 matrices x 64 k-splits in one launch
#define KSPLIT 64
struct VHArgs { const float* W[4]; };
__global__ void vechead_partial(VHArgs a, const float* __restrict__ POOL,
                                float* __restrict__ PART){
    int ks = blockIdx.x;
    int mat = blockIdx.y;                      // 0=st0 1=en0 2=st1 3=en1
    const float* W = a.W[mat];
    const float* PO = POOL + (long)(mat >> 1)*BB*PP*DD;
    int wid = threadIdx.x >> 5, lane = threadIdx.x & 31;
    float acc[4][2] = {{0.f,0.f},{0.f,0.f},{0.f,0.f},{0.f,0.f}};
    int kbase = ks * 512;
    for (int kk = wid; kk < 512; kk += 8){
        int k = kbase + kk;
        float w0 = W[k*64 + lane];
        float w1 = W[k*64 + 32 + lane];
        int p = k & 63, d = k >> 6;
#pragma unroll
        for (int b = 0; b < 4; b++){
            float v = PO[(b*PP + p)*DD + d];
            acc[b][0] = fmaf(v, w0, acc[b][0]);
            acc[b][1] = fmaf(v, w1, acc[b][1]);
        }
    }
    __shared__ float red[8][4][64];
#pragma unroll
    for (int b = 0; b < 4; b++){
        red[wid][b][lane]      = acc[b][0];
        red[wid][b][lane + 32] = acc[b][1];
    }
    __syncthreads();
    int o = threadIdx.x;
    int b = o >> 6, p = o & 63;
    float s = 0.f;
#pragma unroll
    for (int w = 0; w < 8; w++) s += red[w][b][p];
    PART[((mat*KSPLIT + ks)*4 + b)*64 + p] = s;
}

__global__ void vechead_final(const float* __restrict__ PART,
                              const float* __restrict__ b0, const float* __restrict__ b1,
                              const float* __restrict__ b2, const float* __restrict__ b3,
                              float* __restrict__ out){
    int o = blockIdx.x * 256 + threadIdx.x;
    if (o >= 4*4*64) return;
    int mat = o >> 8, rem = o & 255;
    int b = rem >> 6, p = rem & 63;
    float s = 0.f;
#pragma unroll
    for (int ks = 0; ks < KSPLIT; ks++) s += PART[((mat*KSPLIT + ks)*4 + b)*64 + p];
    const float* bias = (mat == 0) ? b0 : (mat == 1) ? b1 : (mat == 2) ? b2 : b3;
    int off = (mat == 0) ? 512 : (mat == 1) ? 768 : (mat == 2) ? 1536 : 1792;
    out[off + b*64 + p] = s + bias[p];
}

// L2 warm-up for st/en weights (32MB); sums into write-only scratch
struct PFArgs { const float* W[4]; };
__global__ void prefetch_kernel(PFArgs a, float* __restrict__ sink){
    float s = 0.f;
    int tid = threadIdx.x;
    const int n4 = 32768*64/4;                 // float4 per matrix
#pragma unroll
    for (int m = 0; m < 4; m++){
        const float4* p = (const float4*)a.W[m];
        for (int i = blockIdx.x*256 + tid; i < n4; i += 256*256){
            float4 v = p[i];
            s += v.x + v.y + v.z + v.w;
        }
    }
    __shared__ float red[256];
    red[tid] = s;
    __syncthreads();
    if (tid == 0){
        float t = 0.f;
        for (int i = 0; i < 256; i++) t += red[i];
        sink[blockIdx.x] = t;
    }
}

// ---------------- launcher ----------------
extern "C" void kernel_launch(void* const* d_in, const int* in_sizes, int n_in,
                              void* d_out, int out_size){
    const float* vis     = (const float*)d_in[0];
    const float* qry     = (const float*)d_in[1];
    const int*   vlen    = (const int*)  d_in[2];
    const float* vid_w1  = (const float*)d_in[3];
    const float* vid_b1  = (const float*)d_in[4];
    const float* vid_w2  = (const float*)d_in[5];
    const float* vid_b2  = (const float*)d_in[6];
    const float* s1_w1   = (const float*)d_in[7];
    const float* s1_b1   = (const float*)d_in[8];
    const float* s1_w2   = (const float*)d_in[9];
    const float* s1_b2   = (const float*)d_in[10];
    const float* s2_w1   = (const float*)d_in[11];
    const float* s2_b1   = (const float*)d_in[12];
    const float* s2_w2   = (const float*)d_in[13];
    const float* s2_b2   = (const float*)d_in[14];
    const float* proj_w  = (const float*)d_in[15];
    const float* proj_b  = (const float*)d_in[16];
    const float* st_w0   = (const float*)d_in[17];
    const float* st_b0   = (const float*)d_in[18];
    const float* en_w0   = (const float*)d_in[19];
    const float* en_b0   = (const float*)d_in[20];
    const float* sg_w0   = (const float*)d_in[21];
    const float* sg_b0   = (const float*)d_in[22];
    const float* st_w1   = (const float*)d_in[23];
    const float* st_b1   = (const float*)d_in[24];
    const float* en_w1   = (const float*)d_in[25];
    const float* en_b1   = (const float*)d_in[26];
    const float* sg_w1   = (const float*)d_in[27];
    const float* sg_b1   = (const float*)d_in[28];
    float* out = (float*)d_out;

    __half *Xvh, *Xvl, *Hh, *Hl, *Xqh, *Xql, *Hqh, *Hql, *Ah, *Al;
    __half *w1h, *w1l, *w2h, *w2l, *pwh, *pwl, *wq1h, *wq1l, *wq2h, *wq2l;
    float *V, *EP, *SIM, *CUM, *PARTS, *Md, *POOL, *PART, *BQ1, *BQ2, *SINK;
    cudaGetSymbolAddress((void**)&Xvh, g_Xvh);
    cudaGetSymbolAddress((void**)&Xvl, g_Xvl);
    cudaGetSymbolAddress((void**)&Hh,  g_Hh);
    cudaGetSymbolAddress((void**)&Hl,  g_Hl);
    cudaGetSymbolAddress((void**)&V,   g_V);
    cudaGetSymbolAddress((void**)&Xqh, g_Xqh);
    cudaGetSymbolAddress((void**)&Xql, g_Xql);
    cudaGetSymbolAddress((void**)&Hqh, g_Hqh);
    cudaGetSymbolAddress((void**)&Hql, g_Hql);
    cudaGetSymbolAddress((void**)&EP,  g_ep);
    cudaGetSymbolAddress((void**)&SIM, g_sim);
    cudaGetSymbolAddress((void**)&CUM, g_cum);
    cudaGetSymbolAddress((void**)&PARTS, g_parts);
    cudaGetSymbolAddress((void**)&Ah,  g_Ah);
    cudaGetSymbolAddress((void**)&Al,  g_Al);
    cudaGetSymbolAddress((void**)&Md,  g_Md);
    cudaGetSymbolAddress((void**)&POOL,g_pool);
    cudaGetSymbolAddress((void**)&PART,g_part);
    cudaGetSymbolAddress((void**)&SINK,g_dummy);
    cudaGetSymbolAddress((void**)&w1h, g_w1h);
    cudaGetSymbolAddress((void**)&w1l, g_w1l);
    cudaGetSymbolAddress((void**)&w2h, g_w2h);
    cudaGetSymbolAddress((void**)&w2l, g_w2l);
    cudaGetSymbolAddress((void**)&pwh, g_pwh);
    cudaGetSymbolAddress((void**)&pwl, g_pwl);
    cudaGetSymbolAddress((void**)&wq1h, g_wq1h);
    cudaGetSymbolAddress((void**)&wq1l, g_wq1l);
    cudaGetSymbolAddress((void**)&wq2h, g_wq2h);
    cudaGetSymbolAddress((void**)&wq2l, g_wq2l);
    cudaGetSymbolAddress((void**)&BQ1, g_bq1);
    cudaGetSymbolAddress((void**)&BQ2, g_bq2);

    cudaFuncSetAttribute(gemm_mma<1,0,1,1>, cudaFuncAttributeMaxDynamicSharedMemorySize, GM_SMEM);
    cudaFuncSetAttribute(gemm_mma<0,1,0,1>, cudaFuncAttributeMaxDynamicSharedMemorySize, GM_SMEM);
    cudaFuncSetAttribute(gemm_mma<0,1,0,0>, cudaFuncAttributeMaxDynamicSharedMemorySize, GM_SMEM);

    // one-time aux stream + events (resources only; work identical each call)
    static cudaStream_t aux = nullptr;
    static cudaEvent_t evF, evT, evPE, evV, evS, evC, evL1, evPF;
    if (aux == nullptr){
        cudaStreamCreateWithFlags(&aux, cudaStreamNonBlocking);
        cudaEventCreateWithFlags(&evF,  cudaEventDisableTiming);
        cudaEventCreateWithFlags(&evT,  cudaEventDisableTiming);
        cudaEventCreateWithFlags(&evPE, cudaEventDisableTiming);
        cudaEventCreateWithFlags(&evV,  cudaEventDisableTiming);
        cudaEventCreateWithFlags(&evS,  cudaEventDisableTiming);
        cudaEventCreateWithFlags(&evC,  cudaEventDisableTiming);
        cudaEventCreateWithFlags(&evL1, cudaEventDisableTiming);
        cudaEventCreateWithFlags(&evPF, cudaEventDisableTiming);
    }

    const int NSW_NONE = 1 << 30;

    // ---- fork at top ----
    cudaEventRecord(evF, 0);
    cudaStreamWaitEvent(aux, evF, 0);

    // aux: weight transposes + bias packs (z=7) — overlaps PE-add on main
    TSArgs ts;
    ts.src[0] = vid_w1; ts.dh[0] = w1h;  ts.dl[0] = w1l;
    ts.src[1] = vid_w2; ts.dh[1] = w2h;  ts.dl[1] = w2l;
    ts.src[2] = proj_w; ts.dh[2] = pwh;  ts.dl[2] = pwl;
    ts.src[3] = s1_w1;  ts.dh[3] = wq1h;           ts.dl[3] = wq1l;
    ts.src[4] = s2_w1;  ts.dh[4] = wq1h + 512*512; ts.dl[4] = wq1l + 512*512;
    ts.src[5] = s1_w2;  ts.dh[5] = wq2h;           ts.dl[5] = wq2l;
    ts.src[6] = s2_w2;  ts.dh[6] = wq2h + 512*512; ts.dl[6] = wq2l + 512*512;
    ts.bsrc[0] = s1_b1; ts.bsrc[1] = s2_b1; ts.bsrc[2] = s1_b2; ts.bsrc[3] = s2_b2;
    ts.bdst1 = BQ1; ts.bdst2 = BQ2;
    transpose_split_all<<<dim3(16,16,8), dim3(32,8), 0, aux>>>(ts);
    cudaEventRecord(evT, aux);

    // main: PE add + split (vis & query; pe computed once per (t,c))
    add_pe_split_all<<<TT, CC>>>(vis, Xvh, Xvl, qry, Xqh, Xql);
    cudaEventRecord(evPE, 0);
    cudaStreamWaitEvent(0, evT, 0);            // vid weights ready

    // aux: enc chain (Xq from PE; weights already on aux timeline)
    cudaStreamWaitEvent(aux, evPE, 0);
    gemm_mma<1,0,1,1><<<dim3(2*CC/64, BB*WN/64), 128, GM_SMEM, aux>>>(
        Xqh, Xql, wq1h, wq1l, BQ1, nullptr, Hqh, Hql, BB*WN, 2*CC, CC, CC, CC, NSW_NONE, 0);
    gemm_mma<0,1,0,1><<<dim3(2*CC/64, BB*WN/64), 128, GM_SMEM, aux>>>(
        Hqh, Hql, wq2h, wq2l, BQ2, EP, nullptr, nullptr, BB*WN, 2*CC, CC, 2*CC, CC, CC, CC);

    // main: vid MLP (3-product: feeds the argmax path)
    gemm_mma<1,0,1,1><<<dim3(CC/64, BB*TT/64), 128, GM_SMEM>>>(
        Xvh, Xvl, w1h, w1l, vid_b1, nullptr, Hh, Hl, BB*TT, CC, CC, CC, CC, NSW_NONE, 0);
    gemm_mma<0,1,0,1><<<dim3(CC/64, BB*TT/64), 128, GM_SMEM>>>(
        Hh, Hl, w2h, w2l, vid_b2, V, nullptr, nullptr, BB*TT, CC, CC, CC, CC, NSW_NONE, 0);
    cudaEventRecord(evV, 0);                   // V ready

    // aux: sim (needs V + EP), concurrent with cumsum on main
    cudaStreamWaitEvent(aux, evV, 0);
    sim_kernel<<<dim3(TT, BB), 256, 0, aux>>>(V, EP, SIM);
    cudaEventRecord(evS, aux);

    // main: chunked prefix sums of v
    cumsum_part_kernel<<<dim3(8, BB), 512>>>(V, PARTS);
    cumsum_write_kernel<<<dim3(8, BB), 512>>>(V, PARTS, CUM);
    cudaEventRecord(evC, 0);

    // aux: labelbuild window 1, then L2 prefetch of head weights (under proj)
    cudaStreamWaitEvent(aux, evC, 0);
    labelbuild_kernel<<<ROWS1, CC, 0, aux>>>(SIM, CUM, EP,
        Ah + (long)AOFF1*CC, Al + (long)AOFF1*CC, NT0_W1, 16);
    cudaEventRecord(evL1, aux);
    PFArgs pf;
    pf.W[0] = st_w0; pf.W[1] = en_w0; pf.W[2] = st_w1; pf.W[3] = en_w1;
    prefetch_kernel<<<256, 256, 0, aux>>>(pf, SINK);
    cudaEventRecord(evPF, aux);

    // main: labelbuild window 0, join lb_w1, ONE merged 2-PRODUCT projection GEMM
    // (labels fixed before this point; A-lo dropped => err ~2^-12, continuous only)
    cudaStreamWaitEvent(0, evS, 0);
    labelbuild_kernel<<<ROWS0, CC>>>(SIM, CUM, EP, Ah, Al, NT0_W0, 8);
    cudaStreamWaitEvent(0, evL1, 0);
    gemm_mma<0,1,0,0><<<dim3(DD/64, 4096/64), 128, GM_SMEM>>>(
        Ah, Al, pwh, pwl, proj_b, Md, nullptr, nullptr, 4096, DD, CC, CC, CC, NSW_NONE, 0);

    // fused pool + seg (both windows), then vechead
    SegArgs sa;
    sa.sw[0] = sg_w0; sa.sb[0] = sg_b0;
    sa.sw[1] = sg_w1; sa.sb[1] = sg_b1;
    pool_seg_kernel<<<dim3(PP, BB, 2), DD>>>(vlen, Md, POOL, sa, out);

    VHArgs vh;
    vh.W[0] = st_w0; vh.W[1] = en_w0; vh.W[2] = st_w1; vh.W[3] = en_w1;
    vechead_partial<<<dim3(KSPLIT, 4), 256>>>(vh, POOL, PART);
    cudaStreamWaitEvent(0, evPF, 0);           // join prefetch (long since done)
    vechead_final<<<4, 256>>>(PART, st_b0, en_b0, st_b1, en_b1, out);
}

// round 17
// speedup vs baseline: 1.3541x; 1.0281x over previous
#include <cuda_runtime.h>
#include <cuda_fp16.h>
#include <math.h>
#include <stdint.h>

// Problem constants (fixed shapes)
#define BB 4
#define TT 512
#define CC 512
#define WN 32
#define DD 512
#define PP 64

#define NT0_W0 (TT-8+1)          // 505
#define NT0_W1 (TT-16+1)         // 497
#define ROWS0 (BB*NT0_W0)        // 2020
#define ROWS1 (BB*NT0_W1)        // 1988
#define AOFF1 2048               // window-1 A/Md row offset (pad rows stay zero)

// ---------------- scratch (static device globals; no allocation) ----------------
__device__ __half g_Xvh[BB*TT*CC], g_Xvl[BB*TT*CC];
__device__ __half g_Hh [BB*TT*CC], g_Hl [BB*TT*CC];
__device__ float g_V  [BB*TT*CC];
__device__ __half g_Xqh[BB*WN*CC], g_Xql[BB*WN*CC];
__device__ __half g_Hqh[BB*WN*2*CC], g_Hql[BB*WN*2*CC];   // [128, 1024]
__device__ float g_ep [BB*WN*2*CC];                        // [128, 1024] = [E1 | E2]
__device__ float g_sim[BB*TT*WN];
__device__ float g_cum[BB*(TT+1)*CC];
__device__ float g_parts[BB*8*CC];
__device__ __half g_Ah[4096*CC], g_Al[4096*CC];   // zero-init; pad rows never written
__device__ float g_Md [4096*DD];
__device__ float g_pool[2*BB*PP*DD];               // per-window buffers
__device__ float g_part[4*64*BB*PP];
__device__ float g_dummy[256];                     // prefetch sink (never read)
__device__ __half g_w1h[CC*CC],   g_w1l[CC*CC];    // vid_w1^T
__device__ __half g_w2h[CC*CC],   g_w2l[CC*CC];    // vid_w2^T
__device__ __half g_pwh[CC*DD],   g_pwl[CC*DD];    // proj_w^T
__device__ __half g_wq1h[2*CC*CC],g_wq1l[2*CC*CC]; // [s1_w1^T ; s2_w1^T]
__device__ __half g_wq2h[2*CC*CC],g_wq2l[2*CC*CC]; // [s1_w2^T ; s2_w2^T]
__device__ float g_bq1[2*CC];                       // [s1_b1 ; s2_b1]
__device__ float g_bq2[2*CC];                       // [s1_b2 ; s2_b2]

static inline int cdiv(int a, int b){ return (a + b - 1) / b; }

// ---------------- mma.sync helpers (sm_80+ path; legal on plain sm_100) ----------------
__device__ __forceinline__ uint32_t smem_to_u32(const void* p) {
    uint32_t a;
    asm("{ .reg .u64 tmp; cvta.to.shared.u64 tmp, %1; cvt.u32.u64 %0, tmp; }" : "=r"(a) : "l"(p));
    return a;
}
__device__ __forceinline__ void ldmx4(uint32_t* r, uint32_t addr){
    asm volatile("ldmatrix.sync.aligned.m8n8.x4.shared.b16 {%0,%1,%2,%3}, [%4];"
        : "=r"(r[0]),"=r"(r[1]),"=r"(r[2]),"=r"(r[3]) : "r"(addr));
}
__device__ __forceinline__ void mma16816(float* c, const uint32_t* a, uint32_t b0, uint32_t b1){
    asm volatile("mma.sync.aligned.m16n8k16.row.col.f32.f16.f16.f32 "
        "{%0,%1,%2,%3}, {%4,%5,%6,%7}, {%8,%9}, {%0,%1,%2,%3};"
        : "+f"(c[0]),"+f"(c[1]),"+f"(c[2]),"+f"(c[3])
        : "r"(a[0]),"r"(a[1]),"r"(a[2]),"r"(a[3]), "r"(b0),"r"(b1));
}
__device__ __forceinline__ void cp_async16(uint32_t saddr, const void* gaddr){
    asm volatile("cp.async.cg.shared.global [%0], [%1], 16;" :: "r"(saddr), "l"(gaddr));
}
// fp16 hi/lo split: hi+lo captures ~22 mantissa bits of v
__device__ __forceinline__ void split_h(float v, __half& h, __half& l){
    h = __float2half_rn(v);
    l = __float2half_rn(v - __half2float(h));
}

// ---------- tensor-core fp16-split GEMM: C = (Ah[+Al])@(Bh[+Bl])^T ----------
// PRODN=3: Ah·Bh + Ah·Bl + Al·Bh (err ~2^-22; argmax-safe)
// PRODN=2: Ah·Bh + Ah·Bl            (err ~2^-12; post-argmax only)
// PRODN=1: Ah·Bh                    (err ~2·2^-12; post-argmax only)
// CSUM=1 (with WF): fused cumsum pass-1 — per-block 64-row column sums of the
// f32 output written to PARTS[(b*8+chunk)*CC + col] (vid GEMM 2 only; M rows
// are b*TT+t with 64-aligned tiles, so each block covers one (b, 64-t-chunk)).
// Block tile 64x64, 4 warps (2m x 2n), warp tile 32x32, K-chunk 32.
// 3-stage smem pipeline + fragment double-buffer. 4 CTAs/SM (128 threads).
// If n0 >= nswitch, A pointers shift by aoff elements (fuses two GEMMs along N).
#define GM_STG 16384
#define GM_SMEM (3*16384)

template<int RELU, int WF, int WS, int PRODN, int CSUM>
__global__ void __launch_bounds__(128, 4)
gemm_mma(const __half* __restrict__ Ah, const __half* __restrict__ Al,
         const __half* __restrict__ Bh, const __half* __restrict__ Bl,
         const float* __restrict__ bias, float* __restrict__ outF,
         __half* __restrict__ outH, __half* __restrict__ outL,
         float* __restrict__ PARTS,
         int M, int N, int K, int lda, int ldb, int nswitch, int aoff)
{
    extern __shared__ char smem[];
    uint32_t sbase = smem_to_u32(smem);
    int tid = threadIdx.x;
    int warp = tid >> 5, lane = tid & 31;
    int wm = warp & 1, wn = warp >> 1;          // 2m x 2n warps
    int m0 = blockIdx.y << 6, n0 = blockIdx.x << 6;
    if (n0 >= nswitch){ Ah += aoff; Al += aoff; }

    float acc[2][4][4];
#pragma unroll
    for (int a = 0; a < 2; a++)
#pragma unroll
        for (int b = 0; b < 4; b++)
#pragma unroll
            for (int c = 0; c < 4; c++) acc[a][b][c] = 0.f;

    int nch = K >> 5;

    auto load_chunk = [&](int ch){
        int stage = ch % 3;
        int k0 = ch << 5;
#pragma unroll
        for (int j = 0; j < 8; j++){
            int i = tid + (j << 7);             // 0..1023
            int tile = i >> 8;                  // 0:Ah 1:Al 2:Bh 3:Bl
            if (PRODN < 3 && tile == 1) continue;  // Al unused
            if (PRODN < 2 && tile == 3) continue;  // Bl unused
            int rem = i & 255;
            int g = rem >> 6, r = rem & 63;
            const __half* gp;
            if (tile < 2) gp = (tile ? Al : Ah) + (long)(m0 + r)*lda + k0 + (g << 3);
            else          gp = ((tile & 1) ? Bl : Bh) + (long)(n0 + r)*ldb + k0 + (g << 3);
            uint32_t sa = sbase + stage*GM_STG + (tile << 12) + (g << 10) + (r << 4);
            cp_async16(sa, gp);
        }
        asm volatile("cp.async.commit_group;");
    };

    load_chunk(0);
    if (nch > 1) load_chunk(1);

    int ra = lane & 15;
    int ghalf = lane >> 4;

    for (int ch = 0; ch < nch; ch++){
        if (ch + 1 < nch) asm volatile("cp.async.wait_group 1;");
        else              asm volatile("cp.async.wait_group 0;");
        __syncthreads();
        if (ch + 2 < nch) load_chunk(ch + 2);

        uint32_t st = sbase + (ch % 3)*GM_STG;

        uint32_t a_h[2][2][4], a_l[2][2][4], b_h[2][2][4], b_l[2][2][4];

        auto load_frag = [&](int ks, int buf){
            int ga = (ks << 1) + ghalf;
#pragma unroll
            for (int mt = 0; mt < 2; mt++){
                int r = (wm << 5) + (mt << 4) + ra;
                uint32_t off = (uint32_t)((ga << 10) + (r << 4));
                ldmx4(a_h[buf][mt], st + off);
                if (PRODN >= 3) ldmx4(a_l[buf][mt], st + 4096 + off);
            }
#pragma unroll
            for (int np = 0; np < 2; np++){
                int r = (wn << 5) + (np << 4) + ra;
                uint32_t off = (uint32_t)((ga << 10) + (r << 4));
                ldmx4(b_h[buf][np], st + 8192  + off);
                if (PRODN >= 2) ldmx4(b_l[buf][np], st + 12288 + off);
            }
        };

        load_frag(0, 0);
#pragma unroll
        for (int ks = 0; ks < 2; ks++){
            int buf = ks & 1;
            if (ks == 0) load_frag(1, 1);
#pragma unroll
            for (int mt = 0; mt < 2; mt++)
#pragma unroll
                for (int nt = 0; nt < 4; nt++){
                    int np = nt >> 1, pr = nt & 1;
                    mma16816(acc[mt][nt], a_h[buf][mt], b_h[buf][np][pr], b_h[buf][np][pr+2]);
                    if (PRODN >= 2)
                        mma16816(acc[mt][nt], a_h[buf][mt], b_l[buf][np][pr], b_l[buf][np][pr+2]);
                    if (PRODN >= 3)
                        mma16816(acc[mt][nt], a_l[buf][mt], b_h[buf][np][pr], b_h[buf][np][pr+2]);
                }
        }
    }
    __syncthreads();

    // epilogue
    int col_base = n0 + (wn << 5);
    int r0 = lane >> 2;
    int cp2 = (lane & 3) << 1;
    float csum[4][2];
    if (CSUM){
#pragma unroll
        for (int nt = 0; nt < 4; nt++){ csum[nt][0] = 0.f; csum[nt][1] = 0.f; }
    }
#pragma unroll
    for (int mt = 0; mt < 2; mt++){
        int row_base = m0 + (wm << 5) + (mt << 4);
#pragma unroll
        for (int i = 0; i < 2; i++){
            int m = row_base + r0 + (i << 3);
#pragma unroll
            for (int nt = 0; nt < 4; nt++){
                int col = col_base + (nt << 3) + cp2;
                float v0 = acc[mt][nt][i*2+0] + bias[col];
                float v1 = acc[mt][nt][i*2+1] + bias[col+1];
                if (RELU){ v0 = fmaxf(v0, 0.f); v1 = fmaxf(v1, 0.f); }
                if (CSUM){ csum[nt][0] += v0; csum[nt][1] += v1; }
                if (WF){
                    float2 o; o.x = v0; o.y = v1;
                    *(float2*)&outF[(long)m*N + col] = o;
                }
                if (WS){
                    __half h0, l0, h1, l1;
                    split_h(v0, h0, l0);
                    split_h(v1, h1, l1);
                    *(__half2*)&outH[(long)m*N + col] = __halves2half2(h0, h1);
                    *(__half2*)&outL[(long)m*N + col] = __halves2half2(l0, l1);
                }
            }
        }
    }
    if (CSUM){
        // reduce over r0 (lanes stride 4): lanes 0..3 end with column sums
        __shared__ float cs[64];
#pragma unroll
        for (int nt = 0; nt < 4; nt++)
#pragma unroll
            for (int j = 0; j < 2; j++){
                float v = csum[nt][j];
                v += __shfl_down_sync(0xffffffffu, v, 4);
                v += __shfl_down_sync(0xffffffffu, v, 8);
                v += __shfl_down_sync(0xffffffffu, v, 16);
                csum[nt][j] = v;
            }
        if (wm == 0 && lane < 4){
#pragma unroll
            for (int nt = 0; nt < 4; nt++)
#pragma unroll
                for (int j = 0; j < 2; j++)
                    cs[(wn << 5) + (nt << 3) + (lane << 1) + j] = csum[nt][j];
        }
        __syncthreads();
        if (wm == 1 && lane < 4){
            int b = m0 >> 9, chunk = (m0 >> 6) & 7;
#pragma unroll
            for (int nt = 0; nt < 4; nt++)
#pragma unroll
                for (int j = 0; j < 2; j++){
                    int cb = (wn << 5) + (nt << 3) + (lane << 1) + j;
                    PARTS[(b*8 + chunk)*CC + n0 + cb] = cs[cb] + csum[nt][j];
                }
        }
    }
}

// ---------------- small kernels ----------------

// PE add + fp16 split. Block per t (512); pe(t,c) computed ONCE, reused across
// the 4 vis rows and (t < WN) the 4 query rows.
__global__ void add_pe_split_all(const float* __restrict__ xv,
                                 __half* __restrict__ xvh, __half* __restrict__ xvl,
                                 const float* __restrict__ xq,
                                 __half* __restrict__ xqh, __half* __restrict__ xql){
    int t = blockIdx.x;        // 0..511
    int c = threadIdx.x;       // 512
    int i2 = (c >> 1) << 1;
    float ang = (float)t * expf((float)i2 * -1.7988946039352293e-2f);
    float pe = (c & 1) ? cosf(ang) : sinf(ang);
#pragma unroll
    for (int b = 0; b < BB; b++){
        long o = ((long)b*TT + t)*CC + c;
        float v = xv[o] + pe;
        __half h, l; split_h(v, h, l);
        xvh[o] = h; xvl[o] = l;
    }
    if (t < WN){
#pragma unroll
        for (int b = 0; b < BB; b++){
            long o = ((long)b*WN + t)*CC + c;
            float v = xq[o] + pe;
            __half h, l; split_h(v, h, l);
            xqh[o] = h; xql[o] = l;
        }
    }
}

// batched 512x512 transpose+split (z=0..6) + bias packing (z=7)
struct TSArgs {
    const float* src[7]; __half* dh[7]; __half* dl[7];
    const float* bsrc[4]; float* bdst1; float* bdst2;
};
__global__ void transpose_split_all(TSArgs a){
    int z = blockIdx.z;
    if (z == 7){
        int idx = (blockIdx.y*16 + blockIdx.x)*256 + threadIdx.y*32 + threadIdx.x;
        if (idx < 2048){
            int seg = idx >> 9, i = idx & 511;
            float v = a.bsrc[seg][i];
            if (seg == 0) a.bdst1[i] = v;
            else if (seg == 1) a.bdst1[512 + i] = v;
            else if (seg == 2) a.bdst2[i] = v;
            else a.bdst2[512 + i] = v;
        }
        return;
    }
    const float* W = a.src[z];
    __half* Th = a.dh[z];
    __half* Tl = a.dl[z];
    __shared__ float t[32][33];
    int bx = blockIdx.x << 5, by = blockIdx.y << 5;
    int x = threadIdx.x, y = threadIdx.y;
#pragma unroll
    for (int i = 0; i < 32; i += 8) t[y+i][x] = W[(long)(by + y + i)*512 + bx + x];
    __syncthreads();
#pragma unroll
    for (int i = 0; i < 32; i += 8){
        float v = t[x][y+i];
        __half h, l; split_h(v, h, l);
        long o = (long)(bx + y + i)*512 + by + x;
        Th[o] = h; Tl[o] = l;
    }
}

// sim[b, t, w] = dot(v[b,t,:], E1[b,w,:]); E1 = EP[:, 0:512] with row stride 1024
__global__ void sim_kernel(const float* __restrict__ V, const float* __restrict__ EP,
                           float* __restrict__ SIM){
    int t = blockIdx.x, b = blockIdx.y;
    __shared__ float vrow[CC];
    int tid = threadIdx.x;
    const float* vp = &V[(b*TT + t)*CC];
    vrow[tid]       = vp[tid];
    vrow[tid + 256] = vp[tid + 256];
    __syncthreads();
    int wid = tid >> 5, lane = tid & 31;
    for (int w = wid; w < WN; w += 8){
        const float* e = &EP[(b*WN + w)*(2*CC)];
        float sum = 0.f;
        for (int c = lane; c < CC; c += 32) sum = fmaf(vrow[c], e[c], sum);
#pragma unroll
        for (int off = 16; off; off >>= 1) sum += __shfl_down_sync(0xffffffffu, sum, off);
        if (lane == 0) SIM[(b*TT + t)*WN + w] = sum;
    }
}

// cumsum pass 2: walk 64 t per block writing exclusive prefix (PARTS from GEMM epilogue)
__global__ void cumsum_write_kernel(const float* __restrict__ V, const float* __restrict__ PARTS,
                                    float* __restrict__ CUM){
    int c = threadIdx.x;
    int chunk = blockIdx.x;
    int b = blockIdx.y;
    float base = 0.f;
    for (int j = 0; j < chunk; j++) base += PARTS[(b*8 + j)*CC + c];
    int t0 = chunk << 6;
    const float* vp = &V[((b*TT) + t0)*CC + c];
    float* cp = &CUM[((b*(TT+1)) + t0)*CC + c];
    float acc = base;
#pragma unroll 8
    for (int u = 0; u < 64; u++){
        cp[u*CC] = acc;
        acc += vp[u*CC];
    }
    if (chunk == 7) cp[64*CC] = acc;
}

// fused labels (warp-0 argmax) + split-A row build; ONE window per launch
__global__ void labelbuild_kernel(const float* __restrict__ SIM, const float* __restrict__ CUM,
                                  const float* __restrict__ EP,
                                  __half* __restrict__ Aho, __half* __restrict__ Alo,
                                  int nt0, int s){
    int row = blockIdx.x;                      // 0..BB*nt0-1
    int b = row / nt0, t0 = row % nt0;
    __shared__ int slab;
    int tid = threadIdx.x;                     // 512
    if (tid < 32){
        const float* sp = &SIM[(b*TT + t0)*WN + tid];
        float sum = 0.f;
        for (int u = 0; u < s; u++) sum += sp[u*WN];
        float best = sum; int bi = tid;
#pragma unroll
        for (int off = 16; off; off >>= 1){
            float ov = __shfl_down_sync(0xffffffffu, best, off);
            int   oi = __shfl_down_sync(0xffffffffu, bi,   off);
            if (ov > best || (ov == best && oi < bi)){ best = ov; bi = oi; }
        }
        if (tid == 0) slab = bi;
    }
    __syncthreads();
    int lab = slab;
    int c = tid;
    float vu = (CUM[(b*(TT+1) + t0 + s)*CC + c] - CUM[(b*(TT+1) + t0)*CC + c]) * (1.f/(float)s);
    float v = vu * EP[(b*WN + lab)*(2*CC) + CC + c];
    __half h, l; split_h(v, h, l);
    Aho[(long)row*CC + c] = h;
    Alo[(long)row*CC + c] = l;
}

// fused adaptive max pool + seg head; z = window (Md rows at 0 / AOFF1)
struct SegArgs { const float* sw[2]; const float* sb[2]; };
__global__ void pool_seg_kernel(const int* __restrict__ vid_len, const float* __restrict__ Md,
                                float* __restrict__ POOL, SegArgs a, float* __restrict__ out){
    int i = blockIdx.x, b = blockIdx.y, z = blockIdx.z;
    int d = threadIdx.x;                       // 512
    int s   = z ? 16 : 8;
    int nt0 = TT - s + 1;
    const float* Mw = Md + (long)(z ? AOFF1 : 0)*DD;
    float* PO = POOL + (long)z*BB*PP*DD;
    int Lin = vid_len[b] * 8;
    if (Lin < 1) Lin = 1;
    int start = (i * Lin) >> 6;
    int end   = ((i + 1) * Lin + 63) >> 6;
    const float* base = Mw + (long)b*nt0*DD + d;
    float m = -3.402823466e38f;
    for (int r = start; r < end; r++){
        int t0 = (r >> 3) + (r & 7) * s;
        float v = base[(long)t0*DD];
        m = fmaxf(m, v);
    }
    PO[(b*PP + i)*DD + d] = m;

    // seg head: dot over d of pooled row with sw[:,0] / sw[:,1]
    const float* sw = a.sw[z];
    float a0 = m * sw[2*d];
    float a1 = m * sw[2*d + 1];
    int lane = d & 31, wid = d >> 5;
#pragma unroll
    for (int off = 16; off; off >>= 1){
        a0 += __shfl_down_sync(0xffffffffu, a0, off);
        a1 += __shfl_down_sync(0xffffffffu, a1, off);
    }
    __shared__ float s0[16], s1[16];
    if (lane == 0){ s0[wid] = a0; s1[wid] = a1; }
    __syncthreads();
    if (d == 0){
        const float* sb = a.sb[z];
        float r0 = 0.f, r1 = 0.f;
#pragma unroll
        for (int w = 0; w < 16; w++){ r0 += s0[w]; r1 += s1[w]; }
        int obase = z ? 1024 : 0;
        out[obase + b*128 + i]      = r0 + sb[0];
        out[obase + b*128 + 64 + i] = r1 + sb[1];
    }
}

// st/en heads: 4 matrices x 64 k-splits in one launch
#define KSPLIT 64
struct VHArgs { const float* W[4]; };
__global__ void vechead_partial(VHArgs a, const float* __restrict__ POOL,
                                float* __restrict__ PART){
    int ks = blockIdx.x;
    int mat = blockIdx.y;                      // 0=st0 1=en0 2=st1 3=en1
    const float* W = a.W[mat];
    const float* PO = POOL + (long)(mat >> 1)*BB*PP*DD;
    int wid = threadIdx.x >> 5, lane = threadIdx.x & 31;
    float acc[4][2] = {{0.f,0.f},{0.f,0.f},{0.f,0.f},{0.f,0.f}};
    int kbase = ks * 512;
    for (int kk = wid; kk < 512; kk += 8){
        int k = kbase + kk;
        float w0 = W[k*64 + lane];
        float w1 = W[k*64 + 32 + lane];
        int p = k & 63, d = k >> 6;
#pragma unroll
        for (int b = 0; b < 4; b++){
            float v = PO[(b*PP + p)*DD + d];
            acc[b][0] = fmaf(v, w0, acc[b][0]);
            acc[b][1] = fmaf(v, w1, acc[b][1]);
        }
    }
    __shared__ float red[8][4][64];
#pragma unroll
    for (int b = 0; b < 4; b++){
        red[wid][b][lane]      = acc[b][0];
        red[wid][b][lane + 32] = acc[b][1];
    }
    __syncthreads();
    int o = threadIdx.x;
    int b = o >> 6, p = o & 63;
    float s = 0.f;
#pragma unroll
    for (int w = 0; w < 8; w++) s += red[w][b][p];
    PART[((mat*KSPLIT + ks)*4 + b)*64 + p] = s;
}

__global__ void vechead_final(const float* __restrict__ PART,
                              const float* __restrict__ b0, const float* __restrict__ b1,
                              const float* __restrict__ b2, const float* __restrict__ b3,
                              float* __restrict__ out){
    int o = blockIdx.x * 256 + threadIdx.x;
    if (o >= 4*4*64) return;
    int mat = o >> 8, rem = o & 255;
    int b = rem >> 6, p = rem & 63;
    float s = 0.f;
#pragma unroll
    for (int ks = 0; ks < KSPLIT; ks++) s += PART[((mat*KSPLIT + ks)*4 + b)*64 + p];
    const float* bias = (mat == 0) ? b0 : (mat == 1) ? b1 : (mat == 2) ? b2 : b3;
    int off = (mat == 0) ? 512 : (mat == 1) ? 768 : (mat == 2) ? 1536 : 1792;
    out[off + b*64 + p] = s + bias[p];
}

// L2 warm-up for st/en weights (32MB); sums into write-only scratch
struct PFArgs { const float* W[4]; };
__global__ void prefetch_kernel(PFArgs a, float* __restrict__ sink){
    float s = 0.f;
    int tid = threadIdx.x;
    const int n4 = 32768*64/4;                 // float4 per matrix
#pragma unroll
    for (int m = 0; m < 4; m++){
        const float4* p = (const float4*)a.W[m];
        for (int i = blockIdx.x*256 + tid; i < n4; i += 256*256){
            float4 v = p[i];
            s += v.x + v.y + v.z + v.w;
        }
    }
    __shared__ float red[256];
    red[tid] = s;
    __syncthreads();
    if (tid == 0){
        float t = 0.f;
        for (int i = 0; i < 256; i++) t += red[i];
        sink[blockIdx.x] = t;
    }
}

// ---------------- launcher ----------------
extern "C" void kernel_launch(void* const* d_in, const int* in_sizes, int n_in,
                              void* d_out, int out_size){
    const float* vis     = (const float*)d_in[0];
    const float* qry     = (const float*)d_in[1];
    const int*   vlen    = (const int*)  d_in[2];
    const float* vid_w1  = (const float*)d_in[3];
    const float* vid_b1  = (const float*)d_in[4];
    const float* vid_w2  = (const float*)d_in[5];
    const float* vid_b2  = (const float*)d_in[6];
    const float* s1_w1   = (const float*)d_in[7];
    const float* s1_b1   = (const float*)d_in[8];
    const float* s1_w2   = (const float*)d_in[9];
    const float* s1_b2   = (const float*)d_in[10];
    const float* s2_w1   = (const float*)d_in[11];
    const float* s2_b1   = (const float*)d_in[12];
    const float* s2_w2   = (const float*)d_in[13];
    const float* s2_b2   = (const float*)d_in[14];
    const float* proj_w  = (const float*)d_in[15];
    const float* proj_b  = (const float*)d_in[16];
    const float* st_w0   = (const float*)d_in[17];
    const float* st_b0   = (const float*)d_in[18];
    const float* en_w0   = (const float*)d_in[19];
    const float* en_b0   = (const float*)d_in[20];
    const float* sg_w0   = (const float*)d_in[21];
    const float* sg_b0   = (const float*)d_in[22];
    const float* st_w1   = (const float*)d_in[23];
    const float* st_b1   = (const float*)d_in[24];
    const float* en_w1   = (const float*)d_in[25];
    const float* en_b1   = (const float*)d_in[26];
    const float* sg_w1   = (const float*)d_in[27];
    const float* sg_b1   = (const float*)d_in[28];
    float* out = (float*)d_out;

    __half *Xvh, *Xvl, *Hh, *Hl, *Xqh, *Xql, *Hqh, *Hql, *Ah, *Al;
    __half *w1h, *w1l, *w2h, *w2l, *pwh, *pwl, *wq1h, *wq1l, *wq2h, *wq2l;
    float *V, *EP, *SIM, *CUM, *PARTS, *Md, *POOL, *PART, *BQ1, *BQ2, *SINK;
    cudaGetSymbolAddress((void**)&Xvh, g_Xvh);
    cudaGetSymbolAddress((void**)&Xvl, g_Xvl);
    cudaGetSymbolAddress((void**)&Hh,  g_Hh);
    cudaGetSymbolAddress((void**)&Hl,  g_Hl);
    cudaGetSymbolAddress((void**)&V,   g_V);
    cudaGetSymbolAddress((void**)&Xqh, g_Xqh);
    cudaGetSymbolAddress((void**)&Xql, g_Xql);
    cudaGetSymbolAddress((void**)&Hqh, g_Hqh);
    cudaGetSymbolAddress((void**)&Hql, g_Hql);
    cudaGetSymbolAddress((void**)&EP,  g_ep);
    cudaGetSymbolAddress((void**)&SIM, g_sim);
    cudaGetSymbolAddress((void**)&CUM, g_cum);
    cudaGetSymbolAddress((void**)&PARTS, g_parts);
    cudaGetSymbolAddress((void**)&Ah,  g_Ah);
    cudaGetSymbolAddress((void**)&Al,  g_Al);
    cudaGetSymbolAddress((void**)&Md,  g_Md);
    cudaGetSymbolAddress((void**)&POOL,g_pool);
    cudaGetSymbolAddress((void**)&PART,g_part);
    cudaGetSymbolAddress((void**)&SINK,g_dummy);
    cudaGetSymbolAddress((void**)&w1h, g_w1h);
    cudaGetSymbolAddress((void**)&w1l, g_w1l);
    cudaGetSymbolAddress((void**)&w2h, g_w2h);
    cudaGetSymbolAddress((void**)&w2l, g_w2l);
    cudaGetSymbolAddress((void**)&pwh, g_pwh);
    cudaGetSymbolAddress((void**)&pwl, g_pwl);
    cudaGetSymbolAddress((void**)&wq1h, g_wq1h);
    cudaGetSymbolAddress((void**)&wq1l, g_wq1l);
    cudaGetSymbolAddress((void**)&wq2h, g_wq2h);
    cudaGetSymbolAddress((void**)&wq2l, g_wq2l);
    cudaGetSymbolAddress((void**)&BQ1, g_bq1);
    cudaGetSymbolAddress((void**)&BQ2, g_bq2);

    cudaFuncSetAttribute(gemm_mma<1,0,1,3,0>, cudaFuncAttributeMaxDynamicSharedMemorySize, GM_SMEM);
    cudaFuncSetAttribute(gemm_mma<0,1,0,3,0>, cudaFuncAttributeMaxDynamicSharedMemorySize, GM_SMEM);
    cudaFuncSetAttribute(gemm_mma<0,1,0,3,1>, cudaFuncAttributeMaxDynamicSharedMemorySize, GM_SMEM);
    cudaFuncSetAttribute(gemm_mma<0,1,0,1,0>, cudaFuncAttributeMaxDynamicSharedMemorySize, GM_SMEM);

    // one-time aux stream + events (resources only; work identical each call)
    static cudaStream_t aux = nullptr;
    static cudaEvent_t evF, evT, evPE, evV, evS, evC, evL1, evPF;
    if (aux == nullptr){
        cudaStreamCreateWithFlags(&aux, cudaStreamNonBlocking);
        cudaEventCreateWithFlags(&evF,  cudaEventDisableTiming);
        cudaEventCreateWithFlags(&evT,  cudaEventDisableTiming);
        cudaEventCreateWithFlags(&evPE, cudaEventDisableTiming);
        cudaEventCreateWithFlags(&evV,  cudaEventDisableTiming);
        cudaEventCreateWithFlags(&evS,  cudaEventDisableTiming);
        cudaEventCreateWithFlags(&evC,  cudaEventDisableTiming);
        cudaEventCreateWithFlags(&evL1, cudaEventDisableTiming);
        cudaEventCreateWithFlags(&evPF, cudaEventDisableTiming);
    }

    const int NSW_NONE = 1 << 30;

    // ---- fork at top ----
    cudaEventRecord(evF, 0);
    cudaStreamWaitEvent(aux, evF, 0);

    // aux: weight transposes + bias packs (z=7) — overlaps PE-add on main
    TSArgs ts;
    ts.src[0] = vid_w1; ts.dh[0] = w1h;  ts.dl[0] = w1l;
    ts.src[1] = vid_w2; ts.dh[1] = w2h;  ts.dl[1] = w2l;
    ts.src[2] = proj_w; ts.dh[2] = pwh;  ts.dl[2] = pwl;
    ts.src[3] = s1_w1;  ts.dh[3] = wq1h;           ts.dl[3] = wq1l;
    ts.src[4] = s2_w1;  ts.dh[4] = wq1h + 512*512; ts.dl[4] = wq1l + 512*512;
    ts.src[5] = s1_w2;  ts.dh[5] = wq2h;           ts.dl[5] = wq2l;
    ts.src[6] = s2_w2;  ts.dh[6] = wq2h + 512*512; ts.dl[6] = wq2l + 512*512;
    ts.bsrc[0] = s1_b1; ts.bsrc[1] = s2_b1; ts.bsrc[2] = s1_b2; ts.bsrc[3] = s2_b2;
    ts.bdst1 = BQ1; ts.bdst2 = BQ2;
    transpose_split_all<<<dim3(16,16,8), dim3(32,8), 0, aux>>>(ts);
    cudaEventRecord(evT, aux);

    // main: PE add + split (vis & query; pe computed once per (t,c))
    add_pe_split_all<<<TT, CC>>>(vis, Xvh, Xvl, qry, Xqh, Xql);
    cudaEventRecord(evPE, 0);
    cudaStreamWaitEvent(0, evT, 0);            // vid weights ready

    // aux: enc chain (Xq from PE; weights already on aux timeline)
    cudaStreamWaitEvent(aux, evPE, 0);
    gemm_mma<1,0,1,3,0><<<dim3(2*CC/64, BB*WN/64), 128, GM_SMEM, aux>>>(
        Xqh, Xql, wq1h, wq1l, BQ1, nullptr, Hqh, Hql, nullptr, BB*WN, 2*CC, CC, CC, CC, NSW_NONE, 0);
    gemm_mma<0,1,0,3,0><<<dim3(2*CC/64, BB*WN/64), 128, GM_SMEM, aux>>>(
        Hqh, Hql, wq2h, wq2l, BQ2, EP, nullptr, nullptr, nullptr, BB*WN, 2*CC, CC, 2*CC, CC, CC, CC);

    // main: vid MLP (3-product: feeds the argmax path); GEMM2 fuses cumsum pass-1
    gemm_mma<1,0,1,3,0><<<dim3(CC/64, BB*TT/64), 128, GM_SMEM>>>(
        Xvh, Xvl, w1h, w1l, vid_b1, nullptr, Hh, Hl, nullptr, BB*TT, CC, CC, CC, CC, NSW_NONE, 0);
    gemm_mma<0,1,0,3,1><<<dim3(CC/64, BB*TT/64), 128, GM_SMEM>>>(
        Hh, Hl, w2h, w2l, vid_b2, V, nullptr, nullptr, PARTS, BB*TT, CC, CC, CC, CC, NSW_NONE, 0);
    cudaEventRecord(evV, 0);                   // V + PARTS ready

    // aux: sim (needs V + EP), concurrent with cumsum pass-2 on main
    cudaStreamWaitEvent(aux, evV, 0);
    sim_kernel<<<dim3(TT, BB), 256, 0, aux>>>(V, EP, SIM);
    cudaEventRecord(evS, aux);

    // main: cumsum pass-2 (PARTS came from the GEMM epilogue)
    cumsum_write_kernel<<<dim3(8, BB), 512>>>(V, PARTS, CUM);
    cudaEventRecord(evC, 0);

    // aux: labelbuild window 1, then L2 prefetch of head weights (under proj)
    cudaStreamWaitEvent(aux, evC, 0);
    labelbuild_kernel<<<ROWS1, CC, 0, aux>>>(SIM, CUM, EP,
        Ah + (long)AOFF1*CC, Al + (long)AOFF1*CC, NT0_W1, 16);
    cudaEventRecord(evL1, aux);
    PFArgs pf;
    pf.W[0] = st_w0; pf.W[1] = en_w0; pf.W[2] = st_w1; pf.W[3] = en_w1;
    prefetch_kernel<<<256, 256, 0, aux>>>(pf, SINK);
    cudaEventRecord(evPF, aux);

    // main: labelbuild window 0, join lb_w1, ONE merged 1-PRODUCT projection GEMM
    // (labels fixed before this point; Ah·Bh only => err ~2·2^-12, continuous)
    cudaStreamWaitEvent(0, evS, 0);
    labelbuild_kernel<<<ROWS0, CC>>>(SIM, CUM, EP, Ah, Al, NT0_W0, 8);
    cudaStreamWaitEvent(0, evL1, 0);
    gemm_mma<0,1,0,1,0><<<dim3(DD/64, 4096/64), 128, GM_SMEM>>>(
        Ah, Al, pwh, pwl, proj_b, Md, nullptr, nullptr, nullptr, 4096, DD, CC, CC, CC, NSW_NONE, 0);

    // fused pool + seg (both windows), then vechead
    SegArgs sa;
    sa.sw[0] = sg_w0; sa.sb[0] = sg_b0;
    sa.sw[1] = sg_w1; sa.sb[1] = sg_b1;
    pool_seg_kernel<<<dim3(PP, BB, 2), DD>>>(vlen, Md, POOL, sa, out);

    VHArgs vh;
    vh.W[0] = st_w0; vh.W[1] = en_w0; vh.W[2] = st_w1; vh.W[3] = en_w1;
    vechead_partial<<<dim3(KSPLIT, 4), 256>>>(vh, POOL, PART);
    cudaStreamWaitEvent(0, evPF, 0);           // join prefetch (long since done)
    vechead_final<<<4, 256>>>(PART, st_b0, en_b0, st_b1, en_b1, out);
}